// round 6
// baseline (speedup 1.0000x reference)
#include <cuda_runtime.h>
#include <cuda_bf16.h>
#include <cstdint>
#include <math.h>

#define B_  2
#define S_  2048
#define D_  1024
#define H_  16
#define DK_ 64
#define M_  (B_ * S_)
#define OUT_ELEMS (B_ * S_ * D_)

// ---------------------------------------------------------------------------
__device__ __forceinline__ uint32_t smem_u32(const void* p) {
    uint32_t a;
    asm("{ .reg .u64 t; cvta.to.shared.u64 t, %1; cvt.u32.u64 %0, t; }" : "=r"(a) : "l"(p));
    return a;
}
#define SWZ128(off) ((off) ^ (((off) >> 3) & 0x70))

__device__ __forceinline__ void cp_async16(uint32_t dst, const void* src) {
    asm volatile("cp.async.cg.shared.global [%0], [%1], 16;" :: "r"(dst), "l"(src));
}
#define CP_COMMIT() asm volatile("cp.async.commit_group;" ::: "memory")
#define CP_WAIT(n)  asm volatile("cp.async.wait_group %0;" :: "n"(n) : "memory")

__device__ __forceinline__ void ldsm4(uint32_t* r, uint32_t addr) {
    asm volatile("ldmatrix.sync.aligned.m8n8.x4.shared.b16 {%0,%1,%2,%3}, [%4];"
                 : "=r"(r[0]), "=r"(r[1]), "=r"(r[2]), "=r"(r[3]) : "r"(addr));
}

__device__ __forceinline__ void mma_bf16(float* c, const uint32_t* a, uint32_t b0, uint32_t b1) {
    asm volatile(
        "mma.sync.aligned.m16n8k16.row.col.f32.bf16.bf16.f32 "
        "{%0,%1,%2,%3}, {%4,%5,%6,%7}, {%8,%9}, {%0,%1,%2,%3};"
        : "+f"(c[0]), "+f"(c[1]), "+f"(c[2]), "+f"(c[3])
        : "r"(a[0]), "r"(a[1]), "r"(a[2]), "r"(a[3]), "r"(b0), "r"(b1));
}

// ---------------------------------------------------------------------------
// Scratch
// ---------------------------------------------------------------------------
__device__ float g_qh[B_ * H_ * S_ * DK_];
__device__ float g_kh[B_ * H_ * S_ * DK_];
__device__ float g_vh[B_ * H_ * S_ * DK_];
__device__ __nv_bfloat16 g_xcat3[3 * M_ * 3 * D_];        // batched A' [4096,3072]
__device__ __nv_bfloat16 g_wcat4[4 * D_ * 3 * D_];        // 4 weights' B' [1024,3072]
__device__ __nv_bfloat16 g_qcat[B_ * H_ * S_ * 3 * DK_];  // [bh][s][hi|lo|hi]
__device__ __nv_bfloat16 g_kcat[B_ * H_ * S_ * 3 * DK_];  // [bh][s][hi|hi|lo]
__device__ __nv_bfloat16 g_vth[B_ * H_ * DK_ * S_];       // V^T hi [bh][d][t]
__device__ __nv_bfloat16 g_vtl[B_ * H_ * DK_ * S_];
__device__ float2 g_part[B_ * H_ * S_ * 16];              // per-tile (max, sumexp)
__device__ float2 g_rowstat[B_ * H_ * S_];                // (max, 1/sum)

// ---------------------------------------------------------------------------
// Split fp32 -> bf16 concat. STYLE 0: [hi|lo|hi]. STYLE 1: [hi|hi|lo].
// ---------------------------------------------------------------------------
template<int KIN, int STYLE>
__global__ __launch_bounds__(256) void split_cat_kernel(
    const float* __restrict__ x, __nv_bfloat16* __restrict__ out)
{
    const int i2 = blockIdx.x * 256 + threadIdx.x;
    const int r  = i2 / (KIN / 2);
    const int kp = (i2 - r * (KIN / 2)) * 2;
    float2 f = *(const float2*)(x + (size_t)r * KIN + kp);
    __nv_bfloat16 h0 = __float2bfloat16(f.x);
    __nv_bfloat16 h1 = __float2bfloat16(f.y);
    __nv_bfloat16 l0 = __float2bfloat16(f.x - __bfloat162float(h0));
    __nv_bfloat16 l1 = __float2bfloat16(f.y - __bfloat162float(h1));
    __nv_bfloat162 hv; hv.x = h0; hv.y = h1;
    __nv_bfloat162 lv; lv.x = l0; lv.y = l1;
    __nv_bfloat16* base = out + (size_t)r * 3 * KIN;
    *(__nv_bfloat162*)(base + kp) = hv;
    if (STYLE == 0) {
        *(__nv_bfloat162*)(base + KIN + kp)     = lv;
        *(__nv_bfloat162*)(base + 2 * KIN + kp) = hv;
    } else {
        *(__nv_bfloat162*)(base + KIN + kp)     = hv;
        *(__nv_bfloat162*)(base + 2 * KIN + kp) = lv;
    }
}

// Transpose 4 weights [1024,1024] fp32 -> [1024,3072] bf16 = [Bh|Bh|Bl]
__global__ __launch_bounds__(256) void transpose_split_cat4_kernel(
    const float* __restrict__ w0, const float* __restrict__ w1,
    const float* __restrict__ w2, const float* __restrict__ w3,
    __nv_bfloat16* __restrict__ outb)
{
    __shared__ float tile[32][33];
    const int z = blockIdx.z;
    const float* w = (z == 0) ? w0 : (z == 1) ? w1 : (z == 2) ? w2 : w3;
    __nv_bfloat16* out = outb + (size_t)z * D_ * 3072;
    const int k0 = blockIdx.y * 32;
    const int n0 = blockIdx.x * 32;
    const int tx = threadIdx.x & 31;
    const int ty = threadIdx.x >> 5;
#pragma unroll
    for (int i = 0; i < 4; i++)
        tile[ty + i * 8][tx] = w[(size_t)(k0 + ty + i * 8) * D_ + n0 + tx];
    __syncthreads();
#pragma unroll
    for (int i = 0; i < 4; i++) {
        float f = tile[tx][ty + i * 8];
        __nv_bfloat16 h = __float2bfloat16(f);
        __nv_bfloat16 l = __float2bfloat16(f - __bfloat162float(h));
        const size_t n = n0 + ty + i * 8;
        const size_t k = k0 + tx;
        out[n * 3072 + k]        = h;
        out[n * 3072 + 1024 + k] = h;
        out[n * 3072 + 2048 + k] = l;
    }
}

// V^T hi/lo: vh [bh][t][64] fp32 -> vth/vtl [bh][64][t] bf16 (smem tiled)
__global__ __launch_bounds__(256) void vtrans_kernel(
    const float* __restrict__ vh, __nv_bfloat16* __restrict__ th, __nv_bfloat16* __restrict__ tl)
{
    __shared__ float tile[32][33];
    const int z = blockIdx.z;
    const int t0 = blockIdx.x * 32;
    const int d0 = blockIdx.y * 32;
    const int tx = threadIdx.x & 31;
    const int ty = threadIdx.x >> 5;
#pragma unroll
    for (int i = 0; i < 4; i++)
        tile[ty + i * 8][tx] = vh[((size_t)z * S_ + t0 + ty + i * 8) * DK_ + d0 + tx];
    __syncthreads();
#pragma unroll
    for (int i = 0; i < 4; i++) {
        float f = tile[tx][ty + i * 8];
        __nv_bfloat16 h = __float2bfloat16(f);
        __nv_bfloat16 l = __float2bfloat16(f - __bfloat162float(h));
        const size_t o = ((size_t)z * DK_ + d0 + ty + i * 8) * S_ + t0 + tx;
        th[o] = h;
        tl[o] = l;
    }
}

// ---------------------------------------------------------------------------
// bf16 mma GEMM. Block 128x128, 8 warps 64x32, BK=64, 3-stage cp.async.
// mode 0: plain C = acc + bias(bq_).
// mode 1: z selects dst (C,C1,C2) + bias (bq_,bk_,bv_); head-split layout.
// mode 3: scores: C = scaled raw scores + per-row (max,sumexp) partials.
// ---------------------------------------------------------------------------
#define GEMM_STAGES 3
#define GEMM_SMEM_SZ (GEMM_STAGES * 32768)

__global__ __launch_bounds__(256) void gemm_mma_kernel(
    const __nv_bfloat16* __restrict__ A, int lda, long long strideA,
    const __nv_bfloat16* __restrict__ B, int ldb, long long strideB,
    float* __restrict__ C, int ldc, long long strideC,
    const float* __restrict__ bq_, const float* __restrict__ bk_,
    const float* __restrict__ bv_,
    float scale, int Kp, int mode,
    float* __restrict__ C1, float* __restrict__ C2,
    float2* __restrict__ part)
{
    extern __shared__ char smem[];
    const uint32_t sbase = smem_u32(smem);
    const int t = threadIdx.x;
    const int lane = t & 31;
    const int wid = t >> 5;
    const int wm = (wid >> 2) * 64;
    const int wn = (wid & 3) * 32;
    const int m0 = blockIdx.y * 128;
    const int n0 = blockIdx.x * 128;
    const int z = blockIdx.z;

    const char* Ab = (const char*)(A + (size_t)z * strideA + (size_t)m0 * lda);
    const char* Bb = (const char*)(B + (size_t)z * strideB + (size_t)n0 * ldb);

    const int ktiles = Kp >> 6;

    auto load_stage = [&](int kt, int s) {
        const uint32_t sa = sbase + (uint32_t)s * 32768u;
#pragma unroll
        for (int i = 0; i < 4; i++) {
            const int id = t + i * 256;
            const int row = id >> 3;
            const int cb = (id & 7) << 4;
            const uint32_t sw = SWZ128((uint32_t)(row * 128 + cb));
            const size_t goff = (size_t)row * lda * 2 + (size_t)kt * 128 + cb;
            const size_t goffB = (size_t)row * ldb * 2 + (size_t)kt * 128 + cb;
            cp_async16(sa + sw, Ab + goff);
            cp_async16(sa + 16384u + sw, Bb + goffB);
        }
        CP_COMMIT();
    };

    float acc[4][4][4];
#pragma unroll
    for (int i = 0; i < 4; i++)
#pragma unroll
        for (int j = 0; j < 4; j++)
#pragma unroll
            for (int k = 0; k < 4; k++) acc[i][j][k] = 0.f;

    load_stage(0, 0);
    if (ktiles > 1) load_stage(1, 1);

    int st = 0;
    for (int kt = 0; kt < ktiles; kt++) {
        if (kt + 2 < ktiles) {
            int s2 = st + 2; if (s2 >= GEMM_STAGES) s2 -= GEMM_STAGES;
            load_stage(kt + 2, s2);
            CP_WAIT(2);
        } else {
            CP_WAIT(0);
        }
        __syncthreads();

        const uint32_t sa = sbase + (uint32_t)st * 32768u;
        const uint32_t sb = sa + 16384u;

#pragma unroll
        for (int ks = 0; ks < 4; ks++) {
            uint32_t af[4][4];
#pragma unroll
            for (int im = 0; im < 4; im++) {
                const int row = wm + im * 16 + (lane & 15);
                const int byt = ks * 32 + ((lane >> 4) << 4);
                ldsm4(af[im], sa + SWZ128((uint32_t)(row * 128 + byt)));
            }
            uint32_t bf[2][4];
#pragma unroll
            for (int j = 0; j < 2; j++) {
                const int nrow = wn + j * 16 + (lane & 7) + ((lane & 16) ? 8 : 0);
                const int byt = ks * 32 + ((lane & 8) ? 16 : 0);
                ldsm4(bf[j], sb + SWZ128((uint32_t)(nrow * 128 + byt)));
            }
#pragma unroll
            for (int im = 0; im < 4; im++)
#pragma unroll
                for (int in = 0; in < 4; in++) {
                    const uint32_t* bb = &bf[in >> 1][(in & 1) * 2];
                    mma_bf16(acc[im][in], af[im], bb[0], bb[1]);
                }
        }
        __syncthreads();
        st++; if (st >= GEMM_STAGES) st = 0;
    }

    if (mode == 0) {
#pragma unroll
        for (int im = 0; im < 4; im++) {
            const int r0 = m0 + wm + im * 16 + (lane >> 2);
#pragma unroll
            for (int in = 0; in < 4; in++) {
                const int col = n0 + wn + in * 8 + (lane & 3) * 2;
                const float b0 = __ldg(bq_ + col), b1 = __ldg(bq_ + col + 1);
                float2 v0, v1;
                v0.x = acc[im][in][0] + b0; v0.y = acc[im][in][1] + b1;
                v1.x = acc[im][in][2] + b0; v1.y = acc[im][in][3] + b1;
                *(float2*)(C + (size_t)r0 * ldc + col) = v0;
                *(float2*)(C + (size_t)(r0 + 8) * ldc + col) = v1;
            }
        }
    } else if (mode == 1) {
        float* dst0 = (z == 0) ? C : (z == 1) ? C1 : C2;
        const float* bp = (z == 0) ? bq_ : (z == 1) ? bk_ : bv_;
#pragma unroll
        for (int im = 0; im < 4; im++) {
            const int r0 = m0 + wm + im * 16 + (lane >> 2);
#pragma unroll
            for (int in = 0; in < 4; in++) {
                const int col = n0 + wn + in * 8 + (lane & 3) * 2;
                const float b0 = __ldg(bp + col), b1 = __ldg(bp + col + 1);
                float2 v0, v1;
                v0.x = acc[im][in][0] + b0; v0.y = acc[im][in][1] + b1;
                v1.x = acc[im][in][2] + b0; v1.y = acc[im][in][3] + b1;
                const int h = col >> 6, d0 = col & 63;
                const int bb0 = r0 >> 11, s0 = r0 & (S_ - 1);
                const int r1 = r0 + 8;
                const int bb1 = r1 >> 11, s1 = r1 & (S_ - 1);
                *(float2*)(dst0 + (((size_t)(bb0 * H_ + h) * S_ + s0) * DK_ + d0)) = v0;
                *(float2*)(dst0 + (((size_t)(bb1 * H_ + h) * S_ + s1) * DK_ + d0)) = v1;
            }
        }
    } else { // mode 3: scores + partials
#pragma unroll
        for (int im = 0; im < 4; im++)
#pragma unroll
            for (int in = 0; in < 4; in++)
#pragma unroll
                for (int k = 0; k < 4; k++) acc[im][in][k] *= scale;

        float* dst0 = C + (size_t)z * strideC;
#pragma unroll
        for (int im = 0; im < 4; im++) {
            const int r0 = m0 + wm + im * 16 + (lane >> 2);
#pragma unroll
            for (int in = 0; in < 4; in++) {
                const int col = n0 + wn + in * 8 + (lane & 3) * 2;
                float2 v0, v1;
                v0.x = acc[im][in][0]; v0.y = acc[im][in][1];
                v1.x = acc[im][in][2]; v1.y = acc[im][in][3];
                *(float2*)(dst0 + (size_t)r0 * ldc + col) = v0;
                *(float2*)(dst0 + (size_t)(r0 + 8) * ldc + col) = v1;
            }
        }
        __syncthreads();
        float2* partS = (float2*)smem;   // [128][4]
#pragma unroll
        for (int im = 0; im < 4; im++) {
#pragma unroll
            for (int half = 0; half < 2; half++) {
                const int rloc = wm + im * 16 + half * 8 + (lane >> 2);
                float vv[8];
#pragma unroll
                for (int in = 0; in < 4; in++) {
                    vv[in * 2 + 0] = acc[im][in][half * 2 + 0];
                    vv[in * 2 + 1] = acc[im][in][half * 2 + 1];
                }
                float m = vv[0];
#pragma unroll
                for (int e = 1; e < 8; e++) m = fmaxf(m, vv[e]);
                m = fmaxf(m, __shfl_xor_sync(0xffffffffu, m, 1));
                m = fmaxf(m, __shfl_xor_sync(0xffffffffu, m, 2));
                float sacc = 0.f;
#pragma unroll
                for (int e = 0; e < 8; e++) sacc += expf(vv[e] - m);
                sacc += __shfl_xor_sync(0xffffffffu, sacc, 1);
                sacc += __shfl_xor_sync(0xffffffffu, sacc, 2);
                if ((lane & 3) == 0) partS[rloc * 4 + (wid & 3)] = make_float2(m, sacc);
            }
        }
        __syncthreads();
        if (t < 128) {
            float2 p0 = partS[t * 4 + 0], p1 = partS[t * 4 + 1];
            float2 p2 = partS[t * 4 + 2], p3 = partS[t * 4 + 3];
            float M = fmaxf(fmaxf(p0.x, p1.x), fmaxf(p2.x, p3.x));
            float S = p0.y * expf(p0.x - M) + p1.y * expf(p1.x - M)
                    + p2.y * expf(p2.x - M) + p3.y * expf(p3.x - M);
            part[((size_t)z * S_ + m0 + t) * 16 + blockIdx.x] = make_float2(M, S);
        }
    }
}

// ---------------------------------------------------------------------------
// Reduce 16 partials per row -> (max, 1/sum). One warp per row.
// ---------------------------------------------------------------------------
__global__ __launch_bounds__(256) void reduce_rowstat_kernel(
    const float2* __restrict__ part, float2* __restrict__ rowstat)
{
    const int row = blockIdx.x * 8 + (threadIdx.x >> 5);
    const int lane = threadIdx.x & 31;
    float2 pr = (lane < 16) ? part[(size_t)row * 16 + lane] : make_float2(-1e30f, 0.f);
    float M = pr.x;
#pragma unroll
    for (int o = 16; o; o >>= 1) M = fmaxf(M, __shfl_xor_sync(0xffffffffu, M, o));
    float s = pr.y * expf(pr.x - M);
#pragma unroll
    for (int o = 16; o; o >>= 1) s += __shfl_xor_sync(0xffffffffu, s, o);
    if (lane == 0) rowstat[row] = make_float2(M, 1.0f / s);
}

// ---------------------------------------------------------------------------
// ctx via mma with fused softmax-normalize + attn writeback.
// ---------------------------------------------------------------------------
#define CTX_STAGE 49152
#define CTX_SMEM (2 * CTX_STAGE + 1024)

__global__ __launch_bounds__(256) void ctx_mma_kernel(
    float* __restrict__ attn, const __nv_bfloat16* __restrict__ vth,
    const __nv_bfloat16* __restrict__ vtl, __nv_bfloat16* __restrict__ xcat,
    const float2* __restrict__ rowstat)
{
    extern __shared__ char smem[];
    const uint32_t sbase = smem_u32(smem);
    const int t = threadIdx.x, lane = t & 31, wid = t >> 5;
    const int wm = (wid >> 1) * 32, wn = (wid & 1) * 32;
    const int z = blockIdx.z, m0 = blockIdx.x * 128;

    float* Ab = attn + ((size_t)z * S_ + m0) * S_;
    const char* Vh = (const char*)(vth + (size_t)z * DK_ * S_);
    const char* Vl = (const char*)(vtl + (size_t)z * DK_ * S_);

    float2* srow = (float2*)(smem + 2 * CTX_STAGE);
    if (t < 128) srow[t] = rowstat[(size_t)z * S_ + m0 + t];

    const int arow = t >> 1, ach = (t & 1) * 32;

    float4 a4[8];
    float acc[2][4][4];
#pragma unroll
    for (int i = 0; i < 2; i++)
#pragma unroll
        for (int j = 0; j < 4; j++)
#pragma unroll
            for (int k = 0; k < 4; k++) acc[i][j][k] = 0.f;

    {
        const float* p = Ab + (size_t)arow * S_ + ach;
#pragma unroll
        for (int j = 0; j < 8; j++) a4[j] = *(const float4*)(p + j * 4);
    }
    {
        const uint32_t vb = sbase + 32768u;
#pragma unroll
        for (int i = 0; i < 2; i++) {
            const int id = t + i * 256;
            const int row = id >> 3, cb = (id & 7) << 4;
            const uint32_t sw = SWZ128((uint32_t)(row * 128 + cb));
            const size_t g = ((size_t)row * S_) * 2 + cb;
            cp_async16(vb + sw, Vh + g);
            cp_async16(vb + 8192u + sw, Vl + g);
        }
        CP_COMMIT();
    }
    __syncthreads();

    const float Mrow = srow[arow].x;
    const float inv = srow[arow].y;

    for (int c = 0; c < 32; c++) {
        const int s = c & 1;
        {
            char* base = smem + s * CTX_STAGE;
            float* wb = Ab + (size_t)arow * S_ + c * 64 + ach;
#pragma unroll
            for (int j = 0; j < 4; j++) {
                float f[8] = {a4[2*j].x, a4[2*j].y, a4[2*j].z, a4[2*j].w,
                              a4[2*j+1].x, a4[2*j+1].y, a4[2*j+1].z, a4[2*j+1].w};
                float p[8];
#pragma unroll
                for (int e = 0; e < 8; e++) p[e] = expf(f[e] - Mrow) * inv;
                float4 w0, w1;
                w0.x = p[0]; w0.y = p[1]; w0.z = p[2]; w0.w = p[3];
                w1.x = p[4]; w1.y = p[5]; w1.z = p[6]; w1.w = p[7];
                *(float4*)(wb + j * 8)     = w0;
                *(float4*)(wb + j * 8 + 4) = w1;
                __nv_bfloat16 hi[8], lo[8];
#pragma unroll
                for (int e = 0; e < 8; e++) {
                    hi[e] = __float2bfloat16(p[e]);
                    lo[e] = __float2bfloat16(p[e] - __bfloat162float(hi[e]));
                }
                const uint32_t off = SWZ128((uint32_t)(arow * 128 + ach * 2 + j * 16));
                *(uint4*)(base + off)         = *(uint4*)hi;
                *(uint4*)(base + 16384 + off) = *(uint4*)lo;
            }
        }
        if (c < 31) {
            const float* p = Ab + (size_t)arow * S_ + (c + 1) * 64 + ach;
#pragma unroll
            for (int j = 0; j < 8; j++) a4[j] = *(const float4*)(p + j * 4);
        }
        CP_WAIT(0);
        __syncthreads();
        if (c < 31) {
            const uint32_t vb = sbase + (uint32_t)(s ^ 1) * CTX_STAGE + 32768u;
#pragma unroll
            for (int i = 0; i < 2; i++) {
                const int id = t + i * 256;
                const int row = id >> 3, cb = (id & 7) << 4;
                const uint32_t sw = SWZ128((uint32_t)(row * 128 + cb));
                const size_t g = ((size_t)row * S_ + (size_t)(c + 1) * 64) * 2 + cb;
                cp_async16(vb + sw, Vh + g);
                cp_async16(vb + 8192u + sw, Vl + g);
            }
            CP_COMMIT();
        }

        const uint32_t sa = sbase + (uint32_t)s * CTX_STAGE;
#pragma unroll
        for (int ks = 0; ks < 4; ks++) {
            uint32_t ah[2][4], al[2][4];
#pragma unroll
            for (int im = 0; im < 2; im++) {
                const int row = wm + im * 16 + (lane & 15);
                const int byt = ks * 32 + ((lane >> 4) << 4);
                const uint32_t o = SWZ128((uint32_t)(row * 128 + byt));
                ldsm4(ah[im], sa + o);
                ldsm4(al[im], sa + 16384u + o);
            }
            uint32_t vhf[2][4], vlf[2][4];
#pragma unroll
            for (int j = 0; j < 2; j++) {
                const int nrow = wn + j * 16 + (lane & 7) + ((lane & 16) ? 8 : 0);
                const int byt = ks * 32 + ((lane & 8) ? 16 : 0);
                const uint32_t o = SWZ128((uint32_t)(nrow * 128 + byt));
                ldsm4(vhf[j], sa + 32768u + o);
                ldsm4(vlf[j], sa + 40960u + o);
            }
#pragma unroll
            for (int im = 0; im < 2; im++)
#pragma unroll
                for (int in = 0; in < 4; in++) {
                    const uint32_t* bh = &vhf[in >> 1][(in & 1) * 2];
                    const uint32_t* bl = &vlf[in >> 1][(in & 1) * 2];
                    mma_bf16(acc[im][in], ah[im], bh[0], bh[1]);
                    mma_bf16(acc[im][in], ah[im], bl[0], bl[1]);
                    mma_bf16(acc[im][in], al[im], bh[0], bh[1]);
                }
        }
    }

    const int bb = z >> 4, h = z & 15;
#pragma unroll
    for (int im = 0; im < 2; im++) {
        const int r0 = m0 + wm + im * 16 + (lane >> 2);
#pragma unroll
        for (int in = 0; in < 4; in++) {
            const int col = wn + in * 8 + (lane & 3) * 2;
            const size_t xcol = (size_t)h * 64 + col;
#pragma unroll
            for (int half = 0; half < 2; half++) {
                const int r = r0 + half * 8;
                const float f0 = acc[im][in][half * 2 + 0];
                const float f1 = acc[im][in][half * 2 + 1];
                __nv_bfloat162 h2, l2;
                h2.x = __float2bfloat16(f0);
                h2.y = __float2bfloat16(f1);
                l2.x = __float2bfloat16(f0 - __bfloat162float(h2.x));
                l2.y = __float2bfloat16(f1 - __bfloat162float(h2.y));
                __nv_bfloat16* row = xcat + ((size_t)bb * S_ + r) * 3072;
                *(__nv_bfloat162*)(row + xcol)        = h2;
                *(__nv_bfloat162*)(row + 1024 + xcol) = l2;
                *(__nv_bfloat162*)(row + 2048 + xcol) = h2;
            }
        }
    }
}

// ---------------------------------------------------------------------------
extern "C" void kernel_launch(void* const* d_in, const int* in_sizes, int n_in,
                              void* d_out, int out_size)
{
    const float* q  = (const float*)d_in[0];
    const float* k  = (const float*)d_in[1];
    const float* v  = (const float*)d_in[2];
    const float* wq = (const float*)d_in[3];
    const float* bq = (const float*)d_in[4];
    const float* wk = (const float*)d_in[5];
    const float* bk = (const float*)d_in[6];
    const float* wv = (const float*)d_in[7];
    const float* bv = (const float*)d_in[8];
    const float* wo = (const float*)d_in[9];
    const float* bo = (const float*)d_in[10];

    float* out  = (float*)d_out;
    float* attn = out + OUT_ELEMS;

    float *qh, *kh, *vh;
    __nv_bfloat16 *xcat3, *wcat4, *qcat, *kcat, *vth, *vtl;
    float2 *part, *rowstat;
    cudaGetSymbolAddress((void**)&qh, g_qh);
    cudaGetSymbolAddress((void**)&kh, g_kh);
    cudaGetSymbolAddress((void**)&vh, g_vh);
    cudaGetSymbolAddress((void**)&xcat3, g_xcat3);
    cudaGetSymbolAddress((void**)&wcat4, g_wcat4);
    cudaGetSymbolAddress((void**)&qcat, g_qcat);
    cudaGetSymbolAddress((void**)&kcat, g_kcat);
    cudaGetSymbolAddress((void**)&vth, g_vth);
    cudaGetSymbolAddress((void**)&vtl, g_vtl);
    cudaGetSymbolAddress((void**)&part, g_part);
    cudaGetSymbolAddress((void**)&rowstat, g_rowstat);

    cudaFuncSetAttribute(gemm_mma_kernel, cudaFuncAttributeMaxDynamicSharedMemorySize, GEMM_SMEM_SZ);
    cudaFuncSetAttribute(ctx_mma_kernel, cudaFuncAttributeMaxDynamicSharedMemorySize, CTX_SMEM);

    const int nSplitX = M_ * (D_ / 2) / 256;
    const int nSplitH = (B_ * H_ * S_) * (DK_ / 2) / 256;
    const long long secX = (long long)M_ * 3 * D_;
    const long long secW = (long long)D_ * 3 * D_;

    // 1. weight transposes (batched)
    transpose_split_cat4_kernel<<<dim3(32, 32, 4), 256>>>(wq, wk, wv, wo, wcat4);
    // 2-4. activation splits
    split_cat_kernel<1024, 0><<<nSplitX, 256>>>(q, xcat3);
    split_cat_kernel<1024, 0><<<nSplitX, 256>>>(k, xcat3 + secX);
    split_cat_kernel<1024, 0><<<nSplitX, 256>>>(v, xcat3 + 2 * secX);

    // 5. QKV projection (mode 1, coalesced permute epilogue -> qh/kh/vh fp32)
    gemm_mma_kernel<<<dim3(8, 32, 3), 256, GEMM_SMEM_SZ>>>(
        xcat3, 3 * D_, secX, wcat4, 3 * D_, secW,
        qh, D_, 0, bq, bk, bv, 1.0f, 3 * D_, 1, kh, vh, nullptr);

    // 6-8. V^T hi/lo + Q/K head splits (coalesced, smem-tiled)
    vtrans_kernel<<<dim3(S_ / 32, DK_ / 32, B_ * H_), 256>>>(vh, vth, vtl);
    split_cat_kernel<64, 0><<<nSplitH, 256>>>(qh, qcat);
    split_cat_kernel<64, 1><<<nSplitH, 256>>>(kh, kcat);

    // 9. scores + softmax partials (mode 3)
    gemm_mma_kernel<<<dim3(16, 16, 32), 256, GEMM_SMEM_SZ>>>(
        qcat, 3 * DK_, (long long)S_ * 3 * DK_,
        kcat, 3 * DK_, (long long)S_ * 3 * DK_,
        attn, S_, (long long)S_ * S_,
        nullptr, nullptr, nullptr, 0.125f, 3 * DK_, 3,
        nullptr, nullptr, part);

    // 10. rowstat reduce
    reduce_rowstat_kernel<<<(B_ * H_ * S_) / 8, 256>>>(part, rowstat);

    // 11. ctx with fused normalize + attn writeback (writes xcat3 sec 0)
    ctx_mma_kernel<<<dim3(16, 1, 32), 256, CTX_SMEM>>>(attn, vth, vtl, xcat3, rowstat);

    // 12. output projection (mode 0)
    gemm_mma_kernel<<<dim3(8, 32, 1), 256, GEMM_SMEM_SZ>>>(
        xcat3, 3 * D_, 0, wcat4 + 3 * secW, 3 * D_, 0,
        out, D_, 0, bo, nullptr, nullptr, 1.0f, 3 * D_, 0,
        nullptr, nullptr, nullptr);
}

// round 7
// speedup vs baseline: 1.1471x; 1.1471x over previous
#include <cuda_runtime.h>
#include <cuda_bf16.h>
#include <cuda_fp16.h>
#include <cstdint>
#include <math.h>

#define B_  2
#define S_  2048
#define D_  1024
#define H_  16
#define DK_ 64
#define M_  (B_ * S_)
#define OUT_ELEMS (B_ * S_ * D_)

// ---------------------------------------------------------------------------
__device__ __forceinline__ uint32_t smem_u32(const void* p) {
    uint32_t a;
    asm("{ .reg .u64 t; cvta.to.shared.u64 t, %1; cvt.u32.u64 %0, t; }" : "=r"(a) : "l"(p));
    return a;
}
#define SWZ128(off) ((off) ^ (((off) >> 3) & 0x70))

__device__ __forceinline__ void cp_async16(uint32_t dst, const void* src) {
    asm volatile("cp.async.cg.shared.global [%0], [%1], 16;" :: "r"(dst), "l"(src));
}
#define CP_COMMIT() asm volatile("cp.async.commit_group;" ::: "memory")
#define CP_WAIT(n)  asm volatile("cp.async.wait_group %0;" :: "n"(n) : "memory")

__device__ __forceinline__ void ldsm4(uint32_t* r, uint32_t addr) {
    asm volatile("ldmatrix.sync.aligned.m8n8.x4.shared.b16 {%0,%1,%2,%3}, [%4];"
                 : "=r"(r[0]), "=r"(r[1]), "=r"(r[2]), "=r"(r[3]) : "r"(addr));
}

__device__ __forceinline__ void mma_bf16(float* c, const uint32_t* a, uint32_t b0, uint32_t b1) {
    asm volatile(
        "mma.sync.aligned.m16n8k16.row.col.f32.bf16.bf16.f32 "
        "{%0,%1,%2,%3}, {%4,%5,%6,%7}, {%8,%9}, {%0,%1,%2,%3};"
        : "+f"(c[0]), "+f"(c[1]), "+f"(c[2]), "+f"(c[3])
        : "r"(a[0]), "r"(a[1]), "r"(a[2]), "r"(a[3]), "r"(b0), "r"(b1));
}

__device__ __forceinline__ void mma_f16(float* c, const uint32_t* a, uint32_t b0, uint32_t b1) {
    asm volatile(
        "mma.sync.aligned.m16n8k16.row.col.f32.f16.f16.f32 "
        "{%0,%1,%2,%3}, {%4,%5,%6,%7}, {%8,%9}, {%0,%1,%2,%3};"
        : "+f"(c[0]), "+f"(c[1]), "+f"(c[2]), "+f"(c[3])
        : "r"(a[0]), "r"(a[1]), "r"(a[2]), "r"(a[3]), "r"(b0), "r"(b1));
}

// ---------------------------------------------------------------------------
// Scratch
// ---------------------------------------------------------------------------
__device__ float g_qh[B_ * H_ * S_ * DK_];
__device__ float g_kh[B_ * H_ * S_ * DK_];
__device__ float g_vh[B_ * H_ * S_ * DK_];
__device__ __nv_bfloat16 g_xcat3[3 * M_ * 3 * D_];        // batched A' [4096,3072]
__device__ __nv_bfloat16 g_wcat4[4 * D_ * 3 * D_];        // 4 weights' B' [1024,3072]
__device__ __nv_bfloat16 g_qcat[B_ * H_ * S_ * 3 * DK_];  // [bh][s][hi|lo|hi]
__device__ __nv_bfloat16 g_kcat[B_ * H_ * S_ * 3 * DK_];  // [bh][s][hi|hi|lo]
__device__ __half g_vth[B_ * H_ * DK_ * S_];              // V^T hi fp16 [bh][d][t]
__device__ __half g_vtl[B_ * H_ * DK_ * S_];              // V^T lo fp16

// ---------------------------------------------------------------------------
// Split fp32 -> bf16 concat. STYLE 0: [hi|lo|hi]. STYLE 1: [hi|hi|lo].
// ---------------------------------------------------------------------------
template<int KIN, int STYLE>
__global__ __launch_bounds__(256) void split_cat_kernel(
    const float* __restrict__ x, __nv_bfloat16* __restrict__ out)
{
    const int i2 = blockIdx.x * 256 + threadIdx.x;
    const int r  = i2 / (KIN / 2);
    const int kp = (i2 - r * (KIN / 2)) * 2;
    float2 f = *(const float2*)(x + (size_t)r * KIN + kp);
    __nv_bfloat16 h0 = __float2bfloat16(f.x);
    __nv_bfloat16 h1 = __float2bfloat16(f.y);
    __nv_bfloat16 l0 = __float2bfloat16(f.x - __bfloat162float(h0));
    __nv_bfloat16 l1 = __float2bfloat16(f.y - __bfloat162float(h1));
    __nv_bfloat162 hv; hv.x = h0; hv.y = h1;
    __nv_bfloat162 lv; lv.x = l0; lv.y = l1;
    __nv_bfloat16* base = out + (size_t)r * 3 * KIN;
    *(__nv_bfloat162*)(base + kp) = hv;
    if (STYLE == 0) {
        *(__nv_bfloat162*)(base + KIN + kp)     = lv;
        *(__nv_bfloat162*)(base + 2 * KIN + kp) = hv;
    } else {
        *(__nv_bfloat162*)(base + KIN + kp)     = hv;
        *(__nv_bfloat162*)(base + 2 * KIN + kp) = lv;
    }
}

// Transpose 4 weights [1024,1024] fp32 -> [1024,3072] bf16 = [Bh|Bh|Bl]
__global__ __launch_bounds__(256) void transpose_split_cat4_kernel(
    const float* __restrict__ w0, const float* __restrict__ w1,
    const float* __restrict__ w2, const float* __restrict__ w3,
    __nv_bfloat16* __restrict__ outb)
{
    __shared__ float tile[32][33];
    const int z = blockIdx.z;
    const float* w = (z == 0) ? w0 : (z == 1) ? w1 : (z == 2) ? w2 : w3;
    __nv_bfloat16* out = outb + (size_t)z * D_ * 3072;
    const int k0 = blockIdx.y * 32;
    const int n0 = blockIdx.x * 32;
    const int tx = threadIdx.x & 31;
    const int ty = threadIdx.x >> 5;
#pragma unroll
    for (int i = 0; i < 4; i++)
        tile[ty + i * 8][tx] = w[(size_t)(k0 + ty + i * 8) * D_ + n0 + tx];
    __syncthreads();
#pragma unroll
    for (int i = 0; i < 4; i++) {
        float f = tile[tx][ty + i * 8];
        __nv_bfloat16 h = __float2bfloat16(f);
        __nv_bfloat16 l = __float2bfloat16(f - __bfloat162float(h));
        const size_t n = n0 + ty + i * 8;
        const size_t k = k0 + tx;
        out[n * 3072 + k]        = h;
        out[n * 3072 + 1024 + k] = h;
        out[n * 3072 + 2048 + k] = l;
    }
}

// V^T hi/lo: vh [bh][t][64] fp32 -> vth/vtl [bh][64][t] fp16 (smem tiled)
__global__ __launch_bounds__(256) void vtrans_kernel(
    const float* __restrict__ vh, __half* __restrict__ th, __half* __restrict__ tl)
{
    __shared__ float tile[32][33];
    const int z = blockIdx.z;
    const int t0 = blockIdx.x * 32;
    const int d0 = blockIdx.y * 32;
    const int tx = threadIdx.x & 31;
    const int ty = threadIdx.x >> 5;
#pragma unroll
    for (int i = 0; i < 4; i++)
        tile[ty + i * 8][tx] = vh[((size_t)z * S_ + t0 + ty + i * 8) * DK_ + d0 + tx];
    __syncthreads();
#pragma unroll
    for (int i = 0; i < 4; i++) {
        float f = tile[tx][ty + i * 8];
        __half h = __float2half(f);
        __half l = __float2half(f - __half2float(h));
        const size_t o = ((size_t)z * DK_ + d0 + ty + i * 8) * S_ + t0 + tx;
        th[o] = h;
        tl[o] = l;
    }
}

// ---------------------------------------------------------------------------
// bf16 mma GEMM. Block 128x128, 8 warps 64x32, BK=64, 3-stage cp.async.
// mode 0: C[z*strideC + m*ldc + col] = scale*acc (+ bias if non-null).
// mode 1: z selects dst (C,C1,C2) + bias (bq_,bk_,bv_); head-split layout.
// ---------------------------------------------------------------------------
#define GEMM_STAGES 3
#define GEMM_SMEM_SZ (GEMM_STAGES * 32768)

__global__ __launch_bounds__(256) void gemm_mma_kernel(
    const __nv_bfloat16* __restrict__ A, int lda, long long strideA,
    const __nv_bfloat16* __restrict__ B, int ldb, long long strideB,
    float* __restrict__ C, int ldc, long long strideC,
    const float* __restrict__ bq_, const float* __restrict__ bk_,
    const float* __restrict__ bv_,
    float scale, int Kp, int mode,
    float* __restrict__ C1, float* __restrict__ C2)
{
    extern __shared__ char smem[];
    const uint32_t sbase = smem_u32(smem);
    const int t = threadIdx.x;
    const int lane = t & 31;
    const int wid = t >> 5;
    const int wm = (wid >> 2) * 64;
    const int wn = (wid & 3) * 32;
    const int m0 = blockIdx.y * 128;
    const int n0 = blockIdx.x * 128;
    const int z = blockIdx.z;

    const char* Ab = (const char*)(A + (size_t)z * strideA + (size_t)m0 * lda);
    const char* Bb = (const char*)(B + (size_t)z * strideB + (size_t)n0 * ldb);

    const int ktiles = Kp >> 6;

    auto load_stage = [&](int kt, int s) {
        const uint32_t sa = sbase + (uint32_t)s * 32768u;
#pragma unroll
        for (int i = 0; i < 4; i++) {
            const int id = t + i * 256;
            const int row = id >> 3;
            const int cb = (id & 7) << 4;
            const uint32_t sw = SWZ128((uint32_t)(row * 128 + cb));
            const size_t goff = (size_t)row * lda * 2 + (size_t)kt * 128 + cb;
            const size_t goffB = (size_t)row * ldb * 2 + (size_t)kt * 128 + cb;
            cp_async16(sa + sw, Ab + goff);
            cp_async16(sa + 16384u + sw, Bb + goffB);
        }
        CP_COMMIT();
    };

    float acc[4][4][4];
#pragma unroll
    for (int i = 0; i < 4; i++)
#pragma unroll
        for (int j = 0; j < 4; j++)
#pragma unroll
            for (int k = 0; k < 4; k++) acc[i][j][k] = 0.f;

    load_stage(0, 0);
    if (ktiles > 1) load_stage(1, 1);

    int st = 0;
    for (int kt = 0; kt < ktiles; kt++) {
        if (kt + 2 < ktiles) {
            int s2 = st + 2; if (s2 >= GEMM_STAGES) s2 -= GEMM_STAGES;
            load_stage(kt + 2, s2);
            CP_WAIT(2);
        } else {
            CP_WAIT(0);
        }
        __syncthreads();

        const uint32_t sa = sbase + (uint32_t)st * 32768u;
        const uint32_t sb = sa + 16384u;

#pragma unroll
        for (int ks = 0; ks < 4; ks++) {
            uint32_t af[4][4];
#pragma unroll
            for (int im = 0; im < 4; im++) {
                const int row = wm + im * 16 + (lane & 15);
                const int byt = ks * 32 + ((lane >> 4) << 4);
                ldsm4(af[im], sa + SWZ128((uint32_t)(row * 128 + byt)));
            }
            uint32_t bf[2][4];
#pragma unroll
            for (int j = 0; j < 2; j++) {
                const int nrow = wn + j * 16 + (lane & 7) + ((lane & 16) ? 8 : 0);
                const int byt = ks * 32 + ((lane & 8) ? 16 : 0);
                ldsm4(bf[j], sb + SWZ128((uint32_t)(nrow * 128 + byt)));
            }
#pragma unroll
            for (int im = 0; im < 4; im++)
#pragma unroll
                for (int in = 0; in < 4; in++) {
                    const uint32_t* bb = &bf[in >> 1][(in & 1) * 2];
                    mma_bf16(acc[im][in], af[im], bb[0], bb[1]);
                }
        }
        __syncthreads();
        st++; if (st >= GEMM_STAGES) st = 0;
    }

    if (mode == 0) {
        float* dst0 = C + (size_t)z * strideC;
#pragma unroll
        for (int im = 0; im < 4; im++) {
            const int r0 = m0 + wm + im * 16 + (lane >> 2);
#pragma unroll
            for (int in = 0; in < 4; in++) {
                const int col = n0 + wn + in * 8 + (lane & 3) * 2;
                float b0 = 0.f, b1 = 0.f;
                if (bq_) { b0 = __ldg(bq_ + col); b1 = __ldg(bq_ + col + 1); }
                float2 v0, v1;
                v0.x = acc[im][in][0] * scale + b0; v0.y = acc[im][in][1] * scale + b1;
                v1.x = acc[im][in][2] * scale + b0; v1.y = acc[im][in][3] * scale + b1;
                *(float2*)(dst0 + (size_t)r0 * ldc + col) = v0;
                *(float2*)(dst0 + (size_t)(r0 + 8) * ldc + col) = v1;
            }
        }
    } else { // mode 1
        float* dst0 = (z == 0) ? C : (z == 1) ? C1 : C2;
        const float* bp = (z == 0) ? bq_ : (z == 1) ? bk_ : bv_;
#pragma unroll
        for (int im = 0; im < 4; im++) {
            const int r0 = m0 + wm + im * 16 + (lane >> 2);
#pragma unroll
            for (int in = 0; in < 4; in++) {
                const int col = n0 + wn + in * 8 + (lane & 3) * 2;
                const float b0 = __ldg(bp + col), b1 = __ldg(bp + col + 1);
                float2 v0, v1;
                v0.x = acc[im][in][0] + b0; v0.y = acc[im][in][1] + b1;
                v1.x = acc[im][in][2] + b0; v1.y = acc[im][in][3] + b1;
                const int h = col >> 6, d0 = col & 63;
                const int bb0 = r0 >> 11, s0 = r0 & (S_ - 1);
                const int r1 = r0 + 8;
                const int bb1 = r1 >> 11, s1 = r1 & (S_ - 1);
                *(float2*)(dst0 + (((size_t)(bb0 * H_ + h) * S_ + s0) * DK_ + d0)) = v0;
                *(float2*)(dst0 + (((size_t)(bb1 * H_ + h) * S_ + s1) * DK_ + d0)) = v1;
            }
        }
    }
}

// ---------------------------------------------------------------------------
// Row softmax in-place (row length 2048), one block/row, float4 vectorized
// ---------------------------------------------------------------------------
__global__ __launch_bounds__(256) void softmax_kernel(float* __restrict__ attn)
{
    const size_t row = blockIdx.x;
    float4* p = (float4*)(attn + row * S_);
    const int t = threadIdx.x;

    float4 v[2];
    float mx = -1e30f;
#pragma unroll
    for (int i = 0; i < 2; i++) {
        v[i] = p[t + 256 * i];
        mx = fmaxf(mx, fmaxf(fmaxf(v[i].x, v[i].y), fmaxf(v[i].z, v[i].w)));
    }
#pragma unroll
    for (int o = 16; o; o >>= 1) mx = fmaxf(mx, __shfl_xor_sync(0xffffffffu, mx, o));

    __shared__ float red[8];
    if ((t & 31) == 0) red[t >> 5] = mx;
    __syncthreads();
    mx = red[0];
#pragma unroll
    for (int i = 1; i < 8; i++) mx = fmaxf(mx, red[i]);
    __syncthreads();

    float sum = 0.f;
#pragma unroll
    for (int i = 0; i < 2; i++) {
        v[i].x = expf(v[i].x - mx); v[i].y = expf(v[i].y - mx);
        v[i].z = expf(v[i].z - mx); v[i].w = expf(v[i].w - mx);
        sum += (v[i].x + v[i].y) + (v[i].z + v[i].w);
    }
#pragma unroll
    for (int o = 16; o; o >>= 1) sum += __shfl_xor_sync(0xffffffffu, sum, o);
    if ((t & 31) == 0) red[t >> 5] = sum;
    __syncthreads();
    sum = 0.f;
#pragma unroll
    for (int i = 0; i < 8; i++) sum += red[i];

    const float inv = 1.0f / sum;
#pragma unroll
    for (int i = 0; i < 2; i++) {
        v[i].x *= inv; v[i].y *= inv; v[i].z *= inv; v[i].w *= inv;
        p[t + 256 * i] = v[i];
    }
}

// ---------------------------------------------------------------------------
// ctx via fp16 mma, 2 products: p_h*v_h + p_h*v_l (p in [0,1], fp16 hi only).
// Reads softmaxed attn fp32, converts to fp16 in-kernel. Writes xcat [hi|lo|hi].
// Block 128x64, 8 warps (4x2, warp 32x32), BK=64, 2-stage.
// Stage: A 16KB + Vh 8KB + Vl 8KB = 32KB.
// ---------------------------------------------------------------------------
#define CTX_STAGE 32768
#define CTX_SMEM (2 * CTX_STAGE)

__global__ __launch_bounds__(256) void ctx_mma_kernel(
    const float* __restrict__ attn, const __half* __restrict__ vth,
    const __half* __restrict__ vtl, __nv_bfloat16* __restrict__ xcat)
{
    extern __shared__ char smem[];
    const uint32_t sbase = smem_u32(smem);
    const int t = threadIdx.x, lane = t & 31, wid = t >> 5;
    const int wm = (wid >> 1) * 32, wn = (wid & 1) * 32;
    const int z = blockIdx.z, m0 = blockIdx.x * 128;

    const float* Ab = attn + ((size_t)z * S_ + m0) * S_;
    const char* Vh = (const char*)(vth + (size_t)z * DK_ * S_);
    const char* Vl = (const char*)(vtl + (size_t)z * DK_ * S_);

    const int arow = t >> 1, ach = (t & 1) * 32;

    float4 a4[8];
    float acc[2][4][4];
#pragma unroll
    for (int i = 0; i < 2; i++)
#pragma unroll
        for (int j = 0; j < 4; j++)
#pragma unroll
            for (int k = 0; k < 4; k++) acc[i][j][k] = 0.f;

    // prologue
    {
        const float* p = Ab + (size_t)arow * S_ + ach;
#pragma unroll
        for (int j = 0; j < 8; j++) a4[j] = *(const float4*)(p + j * 4);
    }
    {
        const uint32_t vb = sbase + 16384u;
#pragma unroll
        for (int i = 0; i < 2; i++) {
            const int id = t + i * 256;
            const int row = id >> 3, cb = (id & 7) << 4;
            const uint32_t sw = SWZ128((uint32_t)(row * 128 + cb));
            const size_t g = ((size_t)row * S_) * 2 + cb;
            cp_async16(vb + sw, Vh + g);
            cp_async16(vb + 8192u + sw, Vl + g);
        }
        CP_COMMIT();
    }

    for (int c = 0; c < 32; c++) {
        const int s = c & 1;
        // convert chunk c to fp16, store to smem
        {
            char* base = smem + s * CTX_STAGE;
#pragma unroll
            for (int j = 0; j < 4; j++) {
                float f[8] = {a4[2*j].x, a4[2*j].y, a4[2*j].z, a4[2*j].w,
                              a4[2*j+1].x, a4[2*j+1].y, a4[2*j+1].z, a4[2*j+1].w};
                __half h[8];
#pragma unroll
                for (int e = 0; e < 8; e++) h[e] = __float2half(f[e]);
                const uint32_t off = SWZ128((uint32_t)(arow * 128 + ach * 2 + j * 16));
                *(uint4*)(base + off) = *(uint4*)h;
            }
        }
        if (c < 31) {
            const float* p = Ab + (size_t)arow * S_ + (c + 1) * 64 + ach;
#pragma unroll
            for (int j = 0; j < 8; j++) a4[j] = *(const float4*)(p + j * 4);
        }
        CP_WAIT(0);
        __syncthreads();
        if (c < 31) {
            const uint32_t vb = sbase + (uint32_t)(s ^ 1) * CTX_STAGE + 16384u;
#pragma unroll
            for (int i = 0; i < 2; i++) {
                const int id = t + i * 256;
                const int row = id >> 3, cb = (id & 7) << 4;
                const uint32_t sw = SWZ128((uint32_t)(row * 128 + cb));
                const size_t g = ((size_t)row * S_ + (size_t)(c + 1) * 64) * 2 + cb;
                cp_async16(vb + sw, Vh + g);
                cp_async16(vb + 8192u + sw, Vl + g);
            }
            CP_COMMIT();
        }

        const uint32_t sa = sbase + (uint32_t)s * CTX_STAGE;
#pragma unroll
        for (int ks = 0; ks < 4; ks++) {
            uint32_t ah[2][4];
#pragma unroll
            for (int im = 0; im < 2; im++) {
                const int row = wm + im * 16 + (lane & 15);
                const int byt = ks * 32 + ((lane >> 4) << 4);
                ldsm4(ah[im], sa + SWZ128((uint32_t)(row * 128 + byt)));
            }
            uint32_t vhf[2][4], vlf[2][4];
#pragma unroll
            for (int j = 0; j < 2; j++) {
                const int nrow = wn + j * 16 + (lane & 7) + ((lane & 16) ? 8 : 0);
                const int byt = ks * 32 + ((lane & 8) ? 16 : 0);
                const uint32_t o = SWZ128((uint32_t)(nrow * 128 + byt));
                ldsm4(vhf[j], sa + 16384u + o);
                ldsm4(vlf[j], sa + 24576u + o);
            }
#pragma unroll
            for (int im = 0; im < 2; im++)
#pragma unroll
                for (int in = 0; in < 4; in++) {
                    const uint32_t* bh = &vhf[in >> 1][(in & 1) * 2];
                    const uint32_t* bl = &vlf[in >> 1][(in & 1) * 2];
                    mma_f16(acc[im][in], ah[im], bh[0], bh[1]);
                    mma_f16(acc[im][in], ah[im], bl[0], bl[1]);
                }
        }
    }

    // epilogue: write xcat [hi|lo|hi]
    const int bb = z >> 4, h = z & 15;
#pragma unroll
    for (int im = 0; im < 2; im++) {
        const int r0 = m0 + wm + im * 16 + (lane >> 2);
#pragma unroll
        for (int in = 0; in < 4; in++) {
            const int col = wn + in * 8 + (lane & 3) * 2;
            const size_t xcol = (size_t)h * 64 + col;
#pragma unroll
            for (int half = 0; half < 2; half++) {
                const int r = r0 + half * 8;
                const float f0 = acc[im][in][half * 2 + 0];
                const float f1 = acc[im][in][half * 2 + 1];
                __nv_bfloat162 h2, l2;
                h2.x = __float2bfloat16(f0);
                h2.y = __float2bfloat16(f1);
                l2.x = __float2bfloat16(f0 - __bfloat162float(h2.x));
                l2.y = __float2bfloat16(f1 - __bfloat162float(h2.y));
                __nv_bfloat16* row = xcat + ((size_t)bb * S_ + r) * 3072;
                *(__nv_bfloat162*)(row + xcol)        = h2;
                *(__nv_bfloat162*)(row + 1024 + xcol) = l2;
                *(__nv_bfloat162*)(row + 2048 + xcol) = h2;
            }
        }
    }
}

// ---------------------------------------------------------------------------
extern "C" void kernel_launch(void* const* d_in, const int* in_sizes, int n_in,
                              void* d_out, int out_size)
{
    const float* q  = (const float*)d_in[0];
    const float* k  = (const float*)d_in[1];
    const float* v  = (const float*)d_in[2];
    const float* wq = (const float*)d_in[3];
    const float* bq = (const float*)d_in[4];
    const float* wk = (const float*)d_in[5];
    const float* bk = (const float*)d_in[6];
    const float* wv = (const float*)d_in[7];
    const float* bv = (const float*)d_in[8];
    const float* wo = (const float*)d_in[9];
    const float* bo = (const float*)d_in[10];

    float* out  = (float*)d_out;
    float* attn = out + OUT_ELEMS;

    float *qh, *kh, *vh;
    __nv_bfloat16 *xcat3, *wcat4, *qcat, *kcat;
    __half *vth, *vtl;
    cudaGetSymbolAddress((void**)&qh, g_qh);
    cudaGetSymbolAddress((void**)&kh, g_kh);
    cudaGetSymbolAddress((void**)&vh, g_vh);
    cudaGetSymbolAddress((void**)&xcat3, g_xcat3);
    cudaGetSymbolAddress((void**)&wcat4, g_wcat4);
    cudaGetSymbolAddress((void**)&qcat, g_qcat);
    cudaGetSymbolAddress((void**)&kcat, g_kcat);
    cudaGetSymbolAddress((void**)&vth, g_vth);
    cudaGetSymbolAddress((void**)&vtl, g_vtl);

    cudaFuncSetAttribute(gemm_mma_kernel, cudaFuncAttributeMaxDynamicSharedMemorySize, GEMM_SMEM_SZ);
    cudaFuncSetAttribute(ctx_mma_kernel, cudaFuncAttributeMaxDynamicSharedMemorySize, CTX_SMEM);

    const int nSplitX = M_ * (D_ / 2) / 256;
    const int nSplitH = (B_ * H_ * S_) * (DK_ / 2) / 256;
    const long long secX = (long long)M_ * 3 * D_;
    const long long secW = (long long)D_ * 3 * D_;

    // 1. weight transposes (batched)
    transpose_split_cat4_kernel<<<dim3(32, 32, 4), 256>>>(wq, wk, wv, wo, wcat4);
    // 2-4. activation splits
    split_cat_kernel<1024, 0><<<nSplitX, 256>>>(q, xcat3);
    split_cat_kernel<1024, 0><<<nSplitX, 256>>>(k, xcat3 + secX);
    split_cat_kernel<1024, 0><<<nSplitX, 256>>>(v, xcat3 + 2 * secX);

    // 5. QKV projection (mode 1 -> qh/kh/vh fp32, head-split layout)
    gemm_mma_kernel<<<dim3(8, 32, 3), 256, GEMM_SMEM_SZ>>>(
        xcat3, 3 * D_, secX, wcat4, 3 * D_, secW,
        qh, D_, 0, bq, bk, bv, 1.0f, 3 * D_, 1, kh, vh);

    // 6-8. V^T fp16 hi/lo + Q/K head splits
    vtrans_kernel<<<dim3(S_ / 32, DK_ / 32, B_ * H_), 256>>>(vh, vth, vtl);
    split_cat_kernel<64, 0><<<nSplitH, 256>>>(qh, qcat);
    split_cat_kernel<64, 1><<<nSplitH, 256>>>(kh, kcat);

    // 9. scores (mode 0, scale 1/8, no bias)
    gemm_mma_kernel<<<dim3(16, 16, 32), 256, GEMM_SMEM_SZ>>>(
        qcat, 3 * DK_, (long long)S_ * 3 * DK_,
        kcat, 3 * DK_, (long long)S_ * 3 * DK_,
        attn, S_, (long long)S_ * S_,
        nullptr, nullptr, nullptr, 0.125f, 3 * DK_, 0, nullptr, nullptr);

    // 10. softmax
    softmax_kernel<<<B_ * H_ * S_, 256>>>(attn);

    // 11. ctx (fp16 2-product, writes xcat3 sec 0)
    ctx_mma_kernel<<<dim3(16, 1, 32), 256, CTX_SMEM>>>(attn, vth, vtl, xcat3);

    // 12. output projection (mode 0 + bias)
    gemm_mma_kernel<<<dim3(8, 32, 1), 256, GEMM_SMEM_SZ>>>(
        xcat3, 3 * D_, 0, wcat4 + 3 * secW, 3 * D_, 0,
        out, D_, 0, bo, nullptr, nullptr, 1.0f, 3 * D_, 0, nullptr, nullptr);
}

// round 8
// speedup vs baseline: 1.2446x; 1.0850x over previous
#include <cuda_runtime.h>
#include <cuda_bf16.h>
#include <cuda_fp16.h>
#include <cstdint>
#include <math.h>

#define B_  2
#define S_  2048
#define D_  1024
#define H_  16
#define DK_ 64
#define M_  (B_ * S_)
#define OUT_ELEMS (B_ * S_ * D_)

// ---------------------------------------------------------------------------
__device__ __forceinline__ uint32_t smem_u32(const void* p) {
    uint32_t a;
    asm("{ .reg .u64 t; cvta.to.shared.u64 t, %1; cvt.u32.u64 %0, t; }" : "=r"(a) : "l"(p));
    return a;
}
#define SWZ128(off) ((off) ^ (((off) >> 3) & 0x70))

__device__ __forceinline__ void cp_async16(uint32_t dst, const void* src) {
    asm volatile("cp.async.cg.shared.global [%0], [%1], 16;" :: "r"(dst), "l"(src));
}
#define CP_COMMIT() asm volatile("cp.async.commit_group;" ::: "memory")
#define CP_WAIT(n)  asm volatile("cp.async.wait_group %0;" :: "n"(n) : "memory")

__device__ __forceinline__ void ldsm4(uint32_t* r, uint32_t addr) {
    asm volatile("ldmatrix.sync.aligned.m8n8.x4.shared.b16 {%0,%1,%2,%3}, [%4];"
                 : "=r"(r[0]), "=r"(r[1]), "=r"(r[2]), "=r"(r[3]) : "r"(addr));
}

__device__ __forceinline__ void mma_bf16(float* c, const uint32_t* a, uint32_t b0, uint32_t b1) {
    asm volatile(
        "mma.sync.aligned.m16n8k16.row.col.f32.bf16.bf16.f32 "
        "{%0,%1,%2,%3}, {%4,%5,%6,%7}, {%8,%9}, {%0,%1,%2,%3};"
        : "+f"(c[0]), "+f"(c[1]), "+f"(c[2]), "+f"(c[3])
        : "r"(a[0]), "r"(a[1]), "r"(a[2]), "r"(a[3]), "r"(b0), "r"(b1));
}

__device__ __forceinline__ void mma_f16(float* c, const uint32_t* a, uint32_t b0, uint32_t b1) {
    asm volatile(
        "mma.sync.aligned.m16n8k16.row.col.f32.f16.f16.f32 "
        "{%0,%1,%2,%3}, {%4,%5,%6,%7}, {%8,%9}, {%0,%1,%2,%3};"
        : "+f"(c[0]), "+f"(c[1]), "+f"(c[2]), "+f"(c[3])
        : "r"(a[0]), "r"(a[1]), "r"(a[2]), "r"(a[3]), "r"(b0), "r"(b1));
}

// ---------------------------------------------------------------------------
// Scratch
// ---------------------------------------------------------------------------
__device__ float g_qh[B_ * H_ * S_ * DK_];
__device__ float g_kh[B_ * H_ * S_ * DK_];
__device__ float g_vh[B_ * H_ * S_ * DK_];
__device__ __nv_bfloat16 g_xcat3[3 * M_ * 3 * D_];        // batched A' [4096,3072]
__device__ __nv_bfloat16 g_wcat4[4 * D_ * 3 * D_];        // 4 weights' B' [1024,3072]
__device__ __nv_bfloat16 g_qcat[B_ * H_ * S_ * 3 * DK_];  // [bh][s][hi|lo|hi]
__device__ __nv_bfloat16 g_kcat[B_ * H_ * S_ * 3 * DK_];  // [bh][s][hi|hi|lo]
__device__ __half g_vth[B_ * H_ * DK_ * S_];              // V^T hi fp16 [bh][d][t]
__device__ __half g_vtl[B_ * H_ * DK_ * S_];              // V^T lo fp16
__device__ __half g_patt[B_ * H_ * S_ * S_];              // softmaxed p fp16

// ---------------------------------------------------------------------------
// Batched activation split: q/k/v fp32 -> bf16 [hi|lo|hi]
// ---------------------------------------------------------------------------
__global__ __launch_bounds__(256) void split_cat3_kernel(
    const float* __restrict__ q, const float* __restrict__ k,
    const float* __restrict__ v, __nv_bfloat16* __restrict__ outb)
{
    const int z = blockIdx.y;
    const float* x = (z == 0) ? q : (z == 1) ? k : v;
    __nv_bfloat16* out = outb + (size_t)z * M_ * 3072;
    const int i2 = blockIdx.x * 256 + threadIdx.x;
    const int r  = i2 >> 9;
    const int kp = (i2 & 511) * 2;
    float2 f = *(const float2*)(x + (size_t)r * 1024 + kp);
    __nv_bfloat16 h0 = __float2bfloat16(f.x);
    __nv_bfloat16 h1 = __float2bfloat16(f.y);
    __nv_bfloat162 hv; hv.x = h0; hv.y = h1;
    __nv_bfloat162 lv;
    lv.x = __float2bfloat16(f.x - __bfloat162float(h0));
    lv.y = __float2bfloat16(f.y - __bfloat162float(h1));
    __nv_bfloat16* base = out + (size_t)r * 3072;
    *(__nv_bfloat162*)(base + kp)        = hv;
    *(__nv_bfloat162*)(base + 1024 + kp) = lv;
    *(__nv_bfloat162*)(base + 2048 + kp) = hv;
}

// Batched head split: qh (style [hi|lo|hi]) and kh (style [hi|hi|lo])
__global__ __launch_bounds__(256) void splitqk_kernel(
    const float* __restrict__ qh, const float* __restrict__ kh,
    __nv_bfloat16* __restrict__ qcat, __nv_bfloat16* __restrict__ kcat)
{
    const int z = blockIdx.y;
    const float* x = (z == 0) ? qh : kh;
    __nv_bfloat16* out = (z == 0) ? qcat : kcat;
    const int i2 = blockIdx.x * 256 + threadIdx.x;
    const int r  = i2 >> 5;
    const int kp = (i2 & 31) * 2;
    float2 f = *(const float2*)(x + (size_t)r * 64 + kp);
    __nv_bfloat16 h0 = __float2bfloat16(f.x);
    __nv_bfloat16 h1 = __float2bfloat16(f.y);
    __nv_bfloat162 hv; hv.x = h0; hv.y = h1;
    __nv_bfloat162 lv;
    lv.x = __float2bfloat16(f.x - __bfloat162float(h0));
    lv.y = __float2bfloat16(f.y - __bfloat162float(h1));
    __nv_bfloat16* base = out + (size_t)r * 192;
    *(__nv_bfloat162*)(base + kp) = hv;
    if (z == 0) {
        *(__nv_bfloat162*)(base + 64 + kp)  = lv;
        *(__nv_bfloat162*)(base + 128 + kp) = hv;
    } else {
        *(__nv_bfloat162*)(base + 64 + kp)  = hv;
        *(__nv_bfloat162*)(base + 128 + kp) = lv;
    }
}

// Transpose 4 weights [1024,1024] fp32 -> [1024,3072] bf16 = [Bh|Bh|Bl]
__global__ __launch_bounds__(256) void transpose_split_cat4_kernel(
    const float* __restrict__ w0, const float* __restrict__ w1,
    const float* __restrict__ w2, const float* __restrict__ w3,
    __nv_bfloat16* __restrict__ outb)
{
    __shared__ float tile[32][33];
    const int z = blockIdx.z;
    const float* w = (z == 0) ? w0 : (z == 1) ? w1 : (z == 2) ? w2 : w3;
    __nv_bfloat16* out = outb + (size_t)z * D_ * 3072;
    const int k0 = blockIdx.y * 32;
    const int n0 = blockIdx.x * 32;
    const int tx = threadIdx.x & 31;
    const int ty = threadIdx.x >> 5;
#pragma unroll
    for (int i = 0; i < 4; i++)
        tile[ty + i * 8][tx] = w[(size_t)(k0 + ty + i * 8) * D_ + n0 + tx];
    __syncthreads();
#pragma unroll
    for (int i = 0; i < 4; i++) {
        float f = tile[tx][ty + i * 8];
        __nv_bfloat16 h = __float2bfloat16(f);
        __nv_bfloat16 l = __float2bfloat16(f - __bfloat162float(h));
        const size_t n = n0 + ty + i * 8;
        const size_t k = k0 + tx;
        out[n * 3072 + k]        = h;
        out[n * 3072 + 1024 + k] = h;
        out[n * 3072 + 2048 + k] = l;
    }
}

// V^T hi/lo: vh [bh][t][64] fp32 -> vth/vtl [bh][64][t] fp16 (smem tiled)
__global__ __launch_bounds__(256) void vtrans_kernel(
    const float* __restrict__ vh, __half* __restrict__ th, __half* __restrict__ tl)
{
    __shared__ float tile[32][33];
    const int z = blockIdx.z;
    const int t0 = blockIdx.x * 32;
    const int d0 = blockIdx.y * 32;
    const int tx = threadIdx.x & 31;
    const int ty = threadIdx.x >> 5;
#pragma unroll
    for (int i = 0; i < 4; i++)
        tile[ty + i * 8][tx] = vh[((size_t)z * S_ + t0 + ty + i * 8) * DK_ + d0 + tx];
    __syncthreads();
#pragma unroll
    for (int i = 0; i < 4; i++) {
        float f = tile[tx][ty + i * 8];
        __half h = __float2half(f);
        __half l = __float2half(f - __half2float(h));
        const size_t o = ((size_t)z * DK_ + d0 + ty + i * 8) * S_ + t0 + tx;
        th[o] = h;
        tl[o] = l;
    }
}

// ---------------------------------------------------------------------------
// bf16 mma GEMM. Block 128x128, 8 warps 64x32, BK=64, 3-stage cp.async.
// mode 0: C[z*strideC + m*ldc + col] = scale*acc (+ bias if non-null).
// mode 1: z selects dst (C,C1,C2) + bias (bq_,bk_,bv_); head-split layout.
// ---------------------------------------------------------------------------
#define GEMM_STAGES 3
#define GEMM_SMEM_SZ (GEMM_STAGES * 32768)

__global__ __launch_bounds__(256) void gemm_mma_kernel(
    const __nv_bfloat16* __restrict__ A, int lda, long long strideA,
    const __nv_bfloat16* __restrict__ B, int ldb, long long strideB,
    float* __restrict__ C, int ldc, long long strideC,
    const float* __restrict__ bq_, const float* __restrict__ bk_,
    const float* __restrict__ bv_,
    float scale, int Kp, int mode,
    float* __restrict__ C1, float* __restrict__ C2)
{
    extern __shared__ char smem[];
    const uint32_t sbase = smem_u32(smem);
    const int t = threadIdx.x;
    const int lane = t & 31;
    const int wid = t >> 5;
    const int wm = (wid >> 2) * 64;
    const int wn = (wid & 3) * 32;
    const int m0 = blockIdx.y * 128;
    const int n0 = blockIdx.x * 128;
    const int z = blockIdx.z;

    const char* Ab = (const char*)(A + (size_t)z * strideA + (size_t)m0 * lda);
    const char* Bb = (const char*)(B + (size_t)z * strideB + (size_t)n0 * ldb);

    const int ktiles = Kp >> 6;

    auto load_stage = [&](int kt, int s) {
        const uint32_t sa = sbase + (uint32_t)s * 32768u;
#pragma unroll
        for (int i = 0; i < 4; i++) {
            const int id = t + i * 256;
            const int row = id >> 3;
            const int cb = (id & 7) << 4;
            const uint32_t sw = SWZ128((uint32_t)(row * 128 + cb));
            const size_t goff = (size_t)row * lda * 2 + (size_t)kt * 128 + cb;
            const size_t goffB = (size_t)row * ldb * 2 + (size_t)kt * 128 + cb;
            cp_async16(sa + sw, Ab + goff);
            cp_async16(sa + 16384u + sw, Bb + goffB);
        }
        CP_COMMIT();
    };

    float acc[4][4][4];
#pragma unroll
    for (int i = 0; i < 4; i++)
#pragma unroll
        for (int j = 0; j < 4; j++)
#pragma unroll
            for (int k = 0; k < 4; k++) acc[i][j][k] = 0.f;

    load_stage(0, 0);
    if (ktiles > 1) load_stage(1, 1);

    int st = 0;
    for (int kt = 0; kt < ktiles; kt++) {
        if (kt + 2 < ktiles) {
            int s2 = st + 2; if (s2 >= GEMM_STAGES) s2 -= GEMM_STAGES;
            load_stage(kt + 2, s2);
            CP_WAIT(2);
        } else {
            CP_WAIT(0);
        }
        __syncthreads();

        const uint32_t sa = sbase + (uint32_t)st * 32768u;
        const uint32_t sb = sa + 16384u;

#pragma unroll
        for (int ks = 0; ks < 4; ks++) {
            uint32_t af[4][4];
#pragma unroll
            for (int im = 0; im < 4; im++) {
                const int row = wm + im * 16 + (lane & 15);
                const int byt = ks * 32 + ((lane >> 4) << 4);
                ldsm4(af[im], sa + SWZ128((uint32_t)(row * 128 + byt)));
            }
            uint32_t bf[2][4];
#pragma unroll
            for (int j = 0; j < 2; j++) {
                const int nrow = wn + j * 16 + (lane & 7) + ((lane & 16) ? 8 : 0);
                const int byt = ks * 32 + ((lane & 8) ? 16 : 0);
                ldsm4(bf[j], sb + SWZ128((uint32_t)(nrow * 128 + byt)));
            }
#pragma unroll
            for (int im = 0; im < 4; im++)
#pragma unroll
                for (int in = 0; in < 4; in++) {
                    const uint32_t* bb = &bf[in >> 1][(in & 1) * 2];
                    mma_bf16(acc[im][in], af[im], bb[0], bb[1]);
                }
        }
        __syncthreads();
        st++; if (st >= GEMM_STAGES) st = 0;
    }

    if (mode == 0) {
        float* dst0 = C + (size_t)z * strideC;
#pragma unroll
        for (int im = 0; im < 4; im++) {
            const int r0 = m0 + wm + im * 16 + (lane >> 2);
#pragma unroll
            for (int in = 0; in < 4; in++) {
                const int col = n0 + wn + in * 8 + (lane & 3) * 2;
                float b0 = 0.f, b1 = 0.f;
                if (bq_) { b0 = __ldg(bq_ + col); b1 = __ldg(bq_ + col + 1); }
                float2 v0, v1;
                v0.x = acc[im][in][0] * scale + b0; v0.y = acc[im][in][1] * scale + b1;
                v1.x = acc[im][in][2] * scale + b0; v1.y = acc[im][in][3] * scale + b1;
                *(float2*)(dst0 + (size_t)r0 * ldc + col) = v0;
                *(float2*)(dst0 + (size_t)(r0 + 8) * ldc + col) = v1;
            }
        }
    } else { // mode 1
        float* dst0 = (z == 0) ? C : (z == 1) ? C1 : C2;
        const float* bp = (z == 0) ? bq_ : (z == 1) ? bk_ : bv_;
#pragma unroll
        for (int im = 0; im < 4; im++) {
            const int r0 = m0 + wm + im * 16 + (lane >> 2);
#pragma unroll
            for (int in = 0; in < 4; in++) {
                const int col = n0 + wn + in * 8 + (lane & 3) * 2;
                const float b0 = __ldg(bp + col), b1 = __ldg(bp + col + 1);
                float2 v0, v1;
                v0.x = acc[im][in][0] + b0; v0.y = acc[im][in][1] + b1;
                v1.x = acc[im][in][2] + b0; v1.y = acc[im][in][3] + b1;
                const int h = col >> 6, d0 = col & 63;
                const int bb0 = r0 >> 11, s0 = r0 & (S_ - 1);
                const int r1 = r0 + 8;
                const int bb1 = r1 >> 11, s1 = r1 & (S_ - 1);
                *(float2*)(dst0 + (((size_t)(bb0 * H_ + h) * S_ + s0) * DK_ + d0)) = v0;
                *(float2*)(dst0 + (((size_t)(bb1 * H_ + h) * S_ + s1) * DK_ + d0)) = v1;
            }
        }
    }
}

// ---------------------------------------------------------------------------
// Row softmax in-place + fp16 normalized copy. One block/row, float4.
// ---------------------------------------------------------------------------
__global__ __launch_bounds__(256) void softmax_kernel(
    float* __restrict__ attn, __half* __restrict__ patt)
{
    const size_t row = blockIdx.x;
    float4* p = (float4*)(attn + row * S_);
    uint2* p16 = (uint2*)(patt + row * S_);
    const int t = threadIdx.x;

    float4 v[2];
    float mx = -1e30f;
#pragma unroll
    for (int i = 0; i < 2; i++) {
        v[i] = p[t + 256 * i];
        mx = fmaxf(mx, fmaxf(fmaxf(v[i].x, v[i].y), fmaxf(v[i].z, v[i].w)));
    }
#pragma unroll
    for (int o = 16; o; o >>= 1) mx = fmaxf(mx, __shfl_xor_sync(0xffffffffu, mx, o));

    __shared__ float red[8];
    if ((t & 31) == 0) red[t >> 5] = mx;
    __syncthreads();
    mx = red[0];
#pragma unroll
    for (int i = 1; i < 8; i++) mx = fmaxf(mx, red[i]);
    __syncthreads();

    float sum = 0.f;
#pragma unroll
    for (int i = 0; i < 2; i++) {
        v[i].x = expf(v[i].x - mx); v[i].y = expf(v[i].y - mx);
        v[i].z = expf(v[i].z - mx); v[i].w = expf(v[i].w - mx);
        sum += (v[i].x + v[i].y) + (v[i].z + v[i].w);
    }
#pragma unroll
    for (int o = 16; o; o >>= 1) sum += __shfl_xor_sync(0xffffffffu, sum, o);
    if ((t & 31) == 0) red[t >> 5] = sum;
    __syncthreads();
    sum = 0.f;
#pragma unroll
    for (int i = 0; i < 8; i++) sum += red[i];

    const float inv = 1.0f / sum;
#pragma unroll
    for (int i = 0; i < 2; i++) {
        v[i].x *= inv; v[i].y *= inv; v[i].z *= inv; v[i].w *= inv;
        p[t + 256 * i] = v[i];
        __half2 a = __floats2half2_rn(v[i].x, v[i].y);
        __half2 b = __floats2half2_rn(v[i].z, v[i].w);
        uint2 u;
        u.x = *(uint32_t*)&a;
        u.y = *(uint32_t*)&b;
        p16[t + 256 * i] = u;
    }
}

// ---------------------------------------------------------------------------
// ctx: clean fp16 GEMM. A = patt [bh][s][2048] fp16, B = V^T hi/lo.
// Block 128x64, 8 warps (4x2, 32x32), BK=64, 3-stage cp.async.
// Stage: A 16KB + Vh 8KB + Vl 8KB = 32KB. Epilogue -> xcat [hi|lo|hi].
// ---------------------------------------------------------------------------
#define CTX_STAGES 3
#define CTX_SMEM (CTX_STAGES * 32768)

__global__ __launch_bounds__(256) void ctx_mma_kernel(
    const __half* __restrict__ patt, const __half* __restrict__ vth,
    const __half* __restrict__ vtl, __nv_bfloat16* __restrict__ xcat)
{
    extern __shared__ char smem[];
    const uint32_t sbase = smem_u32(smem);
    const int t = threadIdx.x, lane = t & 31, wid = t >> 5;
    const int wm = (wid >> 1) * 32, wn = (wid & 1) * 32;
    const int z = blockIdx.z, m0 = blockIdx.x * 128;

    const char* Ab = (const char*)(patt + ((size_t)z * S_ + m0) * S_);
    const char* Vh = (const char*)(vth + (size_t)z * DK_ * S_);
    const char* Vl = (const char*)(vtl + (size_t)z * DK_ * S_);

    auto load_stage = [&](int kt, int s) {
        const uint32_t sa = sbase + (uint32_t)s * 32768u;
#pragma unroll
        for (int i = 0; i < 4; i++) {            // A: 128 rows x 128B
            const int id = t + i * 256;
            const int row = id >> 3;
            const int cb = (id & 7) << 4;
            const uint32_t sw = SWZ128((uint32_t)(row * 128 + cb));
            cp_async16(sa + sw, Ab + (size_t)row * 4096 + (size_t)kt * 128 + cb);
        }
#pragma unroll
        for (int i = 0; i < 2; i++) {            // Vh + Vl: 64 rows x 128B each
            const int id = t + i * 256;
            const int row = id >> 3;
            const int cb = (id & 7) << 4;
            const uint32_t sw = SWZ128((uint32_t)(row * 128 + cb));
            const size_t g = (size_t)row * 4096 + (size_t)kt * 128 + cb;
            cp_async16(sa + 16384u + sw, Vh + g);
            cp_async16(sa + 24576u + sw, Vl + g);
        }
        CP_COMMIT();
    };

    float acc[2][4][4];
#pragma unroll
    for (int i = 0; i < 2; i++)
#pragma unroll
        for (int j = 0; j < 4; j++)
#pragma unroll
            for (int k = 0; k < 4; k++) acc[i][j][k] = 0.f;

    load_stage(0, 0);
    load_stage(1, 1);

    int st = 0;
    for (int kt = 0; kt < 32; kt++) {
        if (kt + 2 < 32) {
            int s2 = st + 2; if (s2 >= CTX_STAGES) s2 -= CTX_STAGES;
            load_stage(kt + 2, s2);
            CP_WAIT(2);
        } else {
            CP_WAIT(0);
        }
        __syncthreads();

        const uint32_t sa = sbase + (uint32_t)st * 32768u;

#pragma unroll
        for (int ks = 0; ks < 4; ks++) {
            uint32_t ah[2][4];
#pragma unroll
            for (int im = 0; im < 2; im++) {
                const int row = wm + im * 16 + (lane & 15);
                const int byt = ks * 32 + ((lane >> 4) << 4);
                ldsm4(ah[im], sa + SWZ128((uint32_t)(row * 128 + byt)));
            }
            uint32_t vhf[2][4], vlf[2][4];
#pragma unroll
            for (int j = 0; j < 2; j++) {
                const int nrow = wn + j * 16 + (lane & 7) + ((lane & 16) ? 8 : 0);
                const int byt = ks * 32 + ((lane & 8) ? 16 : 0);
                const uint32_t o = SWZ128((uint32_t)(nrow * 128 + byt));
                ldsm4(vhf[j], sa + 16384u + o);
                ldsm4(vlf[j], sa + 24576u + o);
            }
#pragma unroll
            for (int im = 0; im < 2; im++)
#pragma unroll
                for (int in = 0; in < 4; in++) {
                    const uint32_t* bh = &vhf[in >> 1][(in & 1) * 2];
                    const uint32_t* bl = &vlf[in >> 1][(in & 1) * 2];
                    mma_f16(acc[im][in], ah[im], bh[0], bh[1]);
                    mma_f16(acc[im][in], ah[im], bl[0], bl[1]);
                }
        }
        __syncthreads();
        st++; if (st >= CTX_STAGES) st = 0;
    }

    // epilogue: write xcat [hi|lo|hi]
    const int bb = z >> 4, h = z & 15;
#pragma unroll
    for (int im = 0; im < 2; im++) {
        const int r0 = m0 + wm + im * 16 + (lane >> 2);
#pragma unroll
        for (int in = 0; in < 4; in++) {
            const int col = wn + in * 8 + (lane & 3) * 2;
            const size_t xcol = (size_t)h * 64 + col;
#pragma unroll
            for (int half = 0; half < 2; half++) {
                const int r = r0 + half * 8;
                const float f0 = acc[im][in][half * 2 + 0];
                const float f1 = acc[im][in][half * 2 + 1];
                __nv_bfloat162 h2, l2;
                h2.x = __float2bfloat16(f0);
                h2.y = __float2bfloat16(f1);
                l2.x = __float2bfloat16(f0 - __bfloat162float(h2.x));
                l2.y = __float2bfloat16(f1 - __bfloat162float(h2.y));
                __nv_bfloat16* row = xcat + ((size_t)bb * S_ + r) * 3072;
                *(__nv_bfloat162*)(row + xcol)        = h2;
                *(__nv_bfloat162*)(row + 1024 + xcol) = l2;
                *(__nv_bfloat162*)(row + 2048 + xcol) = h2;
            }
        }
    }
}

// ---------------------------------------------------------------------------
extern "C" void kernel_launch(void* const* d_in, const int* in_sizes, int n_in,
                              void* d_out, int out_size)
{
    const float* q  = (const float*)d_in[0];
    const float* k  = (const float*)d_in[1];
    const float* v  = (const float*)d_in[2];
    const float* wq = (const float*)d_in[3];
    const float* bq = (const float*)d_in[4];
    const float* wk = (const float*)d_in[5];
    const float* bk = (const float*)d_in[6];
    const float* wv = (const float*)d_in[7];
    const float* bv = (const float*)d_in[8];
    const float* wo = (const float*)d_in[9];
    const float* bo = (const float*)d_in[10];

    float* out  = (float*)d_out;
    float* attn = out + OUT_ELEMS;

    float *qh, *kh, *vh;
    __nv_bfloat16 *xcat3, *wcat4, *qcat, *kcat;
    __half *vth, *vtl, *patt;
    cudaGetSymbolAddress((void**)&qh, g_qh);
    cudaGetSymbolAddress((void**)&kh, g_kh);
    cudaGetSymbolAddress((void**)&vh, g_vh);
    cudaGetSymbolAddress((void**)&xcat3, g_xcat3);
    cudaGetSymbolAddress((void**)&wcat4, g_wcat4);
    cudaGetSymbolAddress((void**)&qcat, g_qcat);
    cudaGetSymbolAddress((void**)&kcat, g_kcat);
    cudaGetSymbolAddress((void**)&vth, g_vth);
    cudaGetSymbolAddress((void**)&vtl, g_vtl);
    cudaGetSymbolAddress((void**)&patt, g_patt);

    cudaFuncSetAttribute(gemm_mma_kernel, cudaFuncAttributeMaxDynamicSharedMemorySize, GEMM_SMEM_SZ);
    cudaFuncSetAttribute(ctx_mma_kernel, cudaFuncAttributeMaxDynamicSharedMemorySize, CTX_SMEM);

    const long long secX = (long long)M_ * 3 * D_;
    const long long secW = (long long)D_ * 3 * D_;

    // 1. weight transposes (batched)
    transpose_split_cat4_kernel<<<dim3(32, 32, 4), 256>>>(wq, wk, wv, wo, wcat4);
    // 2. activation splits (batched z=3)
    split_cat3_kernel<<<dim3(M_ * 512 / 256, 3), 256>>>(q, k, v, xcat3);

    // 3. QKV projection (mode 1 -> qh/kh/vh fp32, head-split layout)
    gemm_mma_kernel<<<dim3(8, 32, 3), 256, GEMM_SMEM_SZ>>>(
        xcat3, 3 * D_, secX, wcat4, 3 * D_, secW,
        qh, D_, 0, bq, bk, bv, 1.0f, 3 * D_, 1, kh, vh);

    // 4. V^T fp16 hi/lo
    vtrans_kernel<<<dim3(S_ / 32, DK_ / 32, B_ * H_), 256>>>(vh, vth, vtl);
    // 5. Q/K head splits (batched z=2)
    splitqk_kernel<<<dim3((B_ * H_ * S_) * 32 / 256, 2), 256>>>(qh, kh, qcat, kcat);

    // 6. scores (mode 0, scale 1/8, no bias)
    gemm_mma_kernel<<<dim3(16, 16, 32), 256, GEMM_SMEM_SZ>>>(
        qcat, 3 * DK_, (long long)S_ * 3 * DK_,
        kcat, 3 * DK_, (long long)S_ * 3 * DK_,
        attn, S_, (long long)S_ * S_,
        nullptr, nullptr, nullptr, 0.125f, 3 * DK_, 0, nullptr, nullptr);

    // 7. softmax (in-place fp32 + fp16 copy)
    softmax_kernel<<<B_ * H_ * S_, 256>>>(attn, patt);

    // 8. ctx (pure fp16 GEMM, writes xcat3 sec 0)
    ctx_mma_kernel<<<dim3(16, 1, 32), 256, CTX_SMEM>>>(patt, vth, vtl, xcat3);

    // 9. output projection (mode 0 + bias)
    gemm_mma_kernel<<<dim3(8, 32, 1), 256, GEMM_SMEM_SZ>>>(
        xcat3, 3 * D_, 0, wcat4 + 3 * secW, 3 * D_, 0,
        out, D_, 0, bo, nullptr, nullptr, 1.0f, 3 * D_, 0, nullptr, nullptr);
}

// round 9
// speedup vs baseline: 1.4024x; 1.1267x over previous
#include <cuda_runtime.h>
#include <cuda_bf16.h>
#include <cuda_fp16.h>
#include <cstdint>
#include <math.h>

#define B_  2
#define S_  2048
#define D_  1024
#define H_  16
#define DK_ 64
#define M_  (B_ * S_)
#define OUT_ELEMS (B_ * S_ * D_)

// ---------------------------------------------------------------------------
__device__ __forceinline__ uint32_t smem_u32(const void* p) {
    uint32_t a;
    asm("{ .reg .u64 t; cvta.to.shared.u64 t, %1; cvt.u32.u64 %0, t; }" : "=r"(a) : "l"(p));
    return a;
}
#define SWZ128(off) ((off) ^ (((off) >> 3) & 0x70))

__device__ __forceinline__ void cp_async16(uint32_t dst, const void* src) {
    asm volatile("cp.async.cg.shared.global [%0], [%1], 16;" :: "r"(dst), "l"(src));
}
#define CP_COMMIT() asm volatile("cp.async.commit_group;" ::: "memory")
#define CP_WAIT(n)  asm volatile("cp.async.wait_group %0;" :: "n"(n) : "memory")

__device__ __forceinline__ void ldsm4(uint32_t* r, uint32_t addr) {
    asm volatile("ldmatrix.sync.aligned.m8n8.x4.shared.b16 {%0,%1,%2,%3}, [%4];"
                 : "=r"(r[0]), "=r"(r[1]), "=r"(r[2]), "=r"(r[3]) : "r"(addr));
}

__device__ __forceinline__ void mma_bf16(float* c, const uint32_t* a, uint32_t b0, uint32_t b1) {
    asm volatile(
        "mma.sync.aligned.m16n8k16.row.col.f32.bf16.bf16.f32 "
        "{%0,%1,%2,%3}, {%4,%5,%6,%7}, {%8,%9}, {%0,%1,%2,%3};"
        : "+f"(c[0]), "+f"(c[1]), "+f"(c[2]), "+f"(c[3])
        : "r"(a[0]), "r"(a[1]), "r"(a[2]), "r"(a[3]), "r"(b0), "r"(b1));
}

__device__ __forceinline__ void mma_f16(float* c, const uint32_t* a, uint32_t b0, uint32_t b1) {
    asm volatile(
        "mma.sync.aligned.m16n8k16.row.col.f32.f16.f16.f32 "
        "{%0,%1,%2,%3}, {%4,%5,%6,%7}, {%8,%9}, {%0,%1,%2,%3};"
        : "+f"(c[0]), "+f"(c[1]), "+f"(c[2]), "+f"(c[3])
        : "r"(a[0]), "r"(a[1]), "r"(a[2]), "r"(a[3]), "r"(b0), "r"(b1));
}

// ---------------------------------------------------------------------------
// Scratch
// ---------------------------------------------------------------------------
__device__ float g_qh[B_ * H_ * S_ * DK_];
__device__ float g_kh[B_ * H_ * S_ * DK_];
__device__ float g_vh[B_ * H_ * S_ * DK_];
__device__ __nv_bfloat16 g_xcat3[3 * M_ * 3 * D_];        // batched A' [4096,3072]
__device__ __nv_bfloat16 g_wcat4[4 * D_ * 3 * D_];        // 4 weights' B' [1024,3072]
__device__ __nv_bfloat16 g_qcat[B_ * H_ * S_ * 3 * DK_];  // [bh][s][hi|lo|hi]
__device__ __nv_bfloat16 g_kcat[B_ * H_ * S_ * 3 * DK_];  // [bh][s][hi|hi|lo]
__device__ __half g_vth[B_ * H_ * DK_ * S_];              // V^T hi fp16 [bh][d][t]
__device__ __half g_vtl[B_ * H_ * DK_ * S_];              // V^T lo fp16
__device__ __half g_patt[B_ * H_ * S_ * S_];              // softmaxed p fp16

// ---------------------------------------------------------------------------
// Batched activation split: q/k/v fp32 -> bf16 [hi|lo|hi]
// ---------------------------------------------------------------------------
__global__ __launch_bounds__(256) void split_cat3_kernel(
    const float* __restrict__ q, const float* __restrict__ k,
    const float* __restrict__ v, __nv_bfloat16* __restrict__ outb)
{
    const int z = blockIdx.y;
    const float* x = (z == 0) ? q : (z == 1) ? k : v;
    __nv_bfloat16* out = outb + (size_t)z * M_ * 3072;
    const int i2 = blockIdx.x * 256 + threadIdx.x;
    const int r  = i2 >> 9;
    const int kp = (i2 & 511) * 2;
    float2 f = *(const float2*)(x + (size_t)r * 1024 + kp);
    __nv_bfloat16 h0 = __float2bfloat16(f.x);
    __nv_bfloat16 h1 = __float2bfloat16(f.y);
    __nv_bfloat162 hv; hv.x = h0; hv.y = h1;
    __nv_bfloat162 lv;
    lv.x = __float2bfloat16(f.x - __bfloat162float(h0));
    lv.y = __float2bfloat16(f.y - __bfloat162float(h1));
    __nv_bfloat16* base = out + (size_t)r * 3072;
    *(__nv_bfloat162*)(base + kp)        = hv;
    *(__nv_bfloat162*)(base + 1024 + kp) = lv;
    *(__nv_bfloat162*)(base + 2048 + kp) = hv;
}

// Batched head split: qh (style [hi|lo|hi]) and kh (style [hi|hi|lo])
__global__ __launch_bounds__(256) void splitqk_kernel(
    const float* __restrict__ qh, const float* __restrict__ kh,
    __nv_bfloat16* __restrict__ qcat, __nv_bfloat16* __restrict__ kcat)
{
    const int z = blockIdx.y;
    const float* x = (z == 0) ? qh : kh;
    __nv_bfloat16* out = (z == 0) ? qcat : kcat;
    const int i2 = blockIdx.x * 256 + threadIdx.x;
    const int r  = i2 >> 5;
    const int kp = (i2 & 31) * 2;
    float2 f = *(const float2*)(x + (size_t)r * 64 + kp);
    __nv_bfloat16 h0 = __float2bfloat16(f.x);
    __nv_bfloat16 h1 = __float2bfloat16(f.y);
    __nv_bfloat162 hv; hv.x = h0; hv.y = h1;
    __nv_bfloat162 lv;
    lv.x = __float2bfloat16(f.x - __bfloat162float(h0));
    lv.y = __float2bfloat16(f.y - __bfloat162float(h1));
    __nv_bfloat16* base = out + (size_t)r * 192;
    *(__nv_bfloat162*)(base + kp) = hv;
    if (z == 0) {
        *(__nv_bfloat162*)(base + 64 + kp)  = lv;
        *(__nv_bfloat162*)(base + 128 + kp) = hv;
    } else {
        *(__nv_bfloat162*)(base + 64 + kp)  = hv;
        *(__nv_bfloat162*)(base + 128 + kp) = lv;
    }
}

// Transpose 4 weights [1024,1024] fp32 -> [1024,3072] bf16 = [Bh|Bh|Bl]
__global__ __launch_bounds__(256) void transpose_split_cat4_kernel(
    const float* __restrict__ w0, const float* __restrict__ w1,
    const float* __restrict__ w2, const float* __restrict__ w3,
    __nv_bfloat16* __restrict__ outb)
{
    __shared__ float tile[32][33];
    const int z = blockIdx.z;
    const float* w = (z == 0) ? w0 : (z == 1) ? w1 : (z == 2) ? w2 : w3;
    __nv_bfloat16* out = outb + (size_t)z * D_ * 3072;
    const int k0 = blockIdx.y * 32;
    const int n0 = blockIdx.x * 32;
    const int tx = threadIdx.x & 31;
    const int ty = threadIdx.x >> 5;
#pragma unroll
    for (int i = 0; i < 4; i++)
        tile[ty + i * 8][tx] = w[(size_t)(k0 + ty + i * 8) * D_ + n0 + tx];
    __syncthreads();
#pragma unroll
    for (int i = 0; i < 4; i++) {
        float f = tile[tx][ty + i * 8];
        __nv_bfloat16 h = __float2bfloat16(f);
        __nv_bfloat16 l = __float2bfloat16(f - __bfloat162float(h));
        const size_t n = n0 + ty + i * 8;
        const size_t k = k0 + tx;
        out[n * 3072 + k]        = h;
        out[n * 3072 + 1024 + k] = h;
        out[n * 3072 + 2048 + k] = l;
    }
}

// V^T hi/lo: vh [bh][t][64] fp32 -> vth/vtl [bh][64][t] fp16 (smem tiled)
__global__ __launch_bounds__(256) void vtrans_kernel(
    const float* __restrict__ vh, __half* __restrict__ th, __half* __restrict__ tl)
{
    __shared__ float tile[32][33];
    const int z = blockIdx.z;
    const int t0 = blockIdx.x * 32;
    const int d0 = blockIdx.y * 32;
    const int tx = threadIdx.x & 31;
    const int ty = threadIdx.x >> 5;
#pragma unroll
    for (int i = 0; i < 4; i++)
        tile[ty + i * 8][tx] = vh[((size_t)z * S_ + t0 + ty + i * 8) * DK_ + d0 + tx];
    __syncthreads();
#pragma unroll
    for (int i = 0; i < 4; i++) {
        float f = tile[tx][ty + i * 8];
        __half h = __float2half(f);
        __half l = __float2half(f - __half2float(h));
        const size_t o = ((size_t)z * DK_ + d0 + ty + i * 8) * S_ + t0 + tx;
        th[o] = h;
        tl[o] = l;
    }
}

// ---------------------------------------------------------------------------
// bf16 mma GEMM. Block 128x128, 8 warps 64x32, BK=64, 3-stage cp.async.
// __launch_bounds__(256,2): cap regs at 128 -> 2 blocks/SM (16 warps).
// mode 0: C[z*strideC + m*ldc + col] = scale*acc (+ bias if non-null).
// mode 1: z selects dst (C,C1,C2) + bias (bq_,bk_,bv_); head-split layout.
// ---------------------------------------------------------------------------
#define GEMM_STAGES 3
#define GEMM_SMEM_SZ (GEMM_STAGES * 32768)

__global__ __launch_bounds__(256, 2) void gemm_mma_kernel(
    const __nv_bfloat16* __restrict__ A, int lda, long long strideA,
    const __nv_bfloat16* __restrict__ B, int ldb, long long strideB,
    float* __restrict__ C, int ldc, long long strideC,
    const float* __restrict__ bq_, const float* __restrict__ bk_,
    const float* __restrict__ bv_,
    float scale, int Kp, int mode,
    float* __restrict__ C1, float* __restrict__ C2)
{
    extern __shared__ char smem[];
    const uint32_t sbase = smem_u32(smem);
    const int t = threadIdx.x;
    const int lane = t & 31;
    const int wid = t >> 5;
    const int wm = (wid >> 2) * 64;
    const int wn = (wid & 3) * 32;
    const int m0 = blockIdx.y * 128;
    const int n0 = blockIdx.x * 128;
    const int z = blockIdx.z;

    const char* Ab = (const char*)(A + (size_t)z * strideA + (size_t)m0 * lda);
    const char* Bb = (const char*)(B + (size_t)z * strideB + (size_t)n0 * ldb);

    const int ktiles = Kp >> 6;

    auto load_stage = [&](int kt, int s) {
        const uint32_t sa = sbase + (uint32_t)s * 32768u;
#pragma unroll
        for (int i = 0; i < 4; i++) {
            const int id = t + i * 256;
            const int row = id >> 3;
            const int cb = (id & 7) << 4;
            const uint32_t sw = SWZ128((uint32_t)(row * 128 + cb));
            const size_t goff = (size_t)row * lda * 2 + (size_t)kt * 128 + cb;
            const size_t goffB = (size_t)row * ldb * 2 + (size_t)kt * 128 + cb;
            cp_async16(sa + sw, Ab + goff);
            cp_async16(sa + 16384u + sw, Bb + goffB);
        }
        CP_COMMIT();
    };

    float acc[4][4][4];
#pragma unroll
    for (int i = 0; i < 4; i++)
#pragma unroll
        for (int j = 0; j < 4; j++)
#pragma unroll
            for (int k = 0; k < 4; k++) acc[i][j][k] = 0.f;

    load_stage(0, 0);
    if (ktiles > 1) load_stage(1, 1);

    int st = 0;
    for (int kt = 0; kt < ktiles; kt++) {
        if (kt + 2 < ktiles) {
            int s2 = st + 2; if (s2 >= GEMM_STAGES) s2 -= GEMM_STAGES;
            load_stage(kt + 2, s2);
            CP_WAIT(2);
        } else {
            CP_WAIT(0);
        }
        __syncthreads();

        const uint32_t sa = sbase + (uint32_t)st * 32768u;
        const uint32_t sb = sa + 16384u;

#pragma unroll
        for (int ks = 0; ks < 4; ks++) {
            uint32_t af[4][4];
#pragma unroll
            for (int im = 0; im < 4; im++) {
                const int row = wm + im * 16 + (lane & 15);
                const int byt = ks * 32 + ((lane >> 4) << 4);
                ldsm4(af[im], sa + SWZ128((uint32_t)(row * 128 + byt)));
            }
            uint32_t bf[2][4];
#pragma unroll
            for (int j = 0; j < 2; j++) {
                const int nrow = wn + j * 16 + (lane & 7) + ((lane & 16) ? 8 : 0);
                const int byt = ks * 32 + ((lane & 8) ? 16 : 0);
                ldsm4(bf[j], sb + SWZ128((uint32_t)(nrow * 128 + byt)));
            }
#pragma unroll
            for (int im = 0; im < 4; im++)
#pragma unroll
                for (int in = 0; in < 4; in++) {
                    const uint32_t* bb = &bf[in >> 1][(in & 1) * 2];
                    mma_bf16(acc[im][in], af[im], bb[0], bb[1]);
                }
        }
        __syncthreads();
        st++; if (st >= GEMM_STAGES) st = 0;
    }

    if (mode == 0) {
        float* dst0 = C + (size_t)z * strideC;
#pragma unroll
        for (int im = 0; im < 4; im++) {
            const int r0 = m0 + wm + im * 16 + (lane >> 2);
#pragma unroll
            for (int in = 0; in < 4; in++) {
                const int col = n0 + wn + in * 8 + (lane & 3) * 2;
                float b0 = 0.f, b1 = 0.f;
                if (bq_) { b0 = __ldg(bq_ + col); b1 = __ldg(bq_ + col + 1); }
                float2 v0, v1;
                v0.x = acc[im][in][0] * scale + b0; v0.y = acc[im][in][1] * scale + b1;
                v1.x = acc[im][in][2] * scale + b0; v1.y = acc[im][in][3] * scale + b1;
                *(float2*)(dst0 + (size_t)r0 * ldc + col) = v0;
                *(float2*)(dst0 + (size_t)(r0 + 8) * ldc + col) = v1;
            }
        }
    } else { // mode 1
        float* dst0 = (z == 0) ? C : (z == 1) ? C1 : C2;
        const float* bp = (z == 0) ? bq_ : (z == 1) ? bk_ : bv_;
#pragma unroll
        for (int im = 0; im < 4; im++) {
            const int r0 = m0 + wm + im * 16 + (lane >> 2);
#pragma unroll
            for (int in = 0; in < 4; in++) {
                const int col = n0 + wn + in * 8 + (lane & 3) * 2;
                const float b0 = __ldg(bp + col), b1 = __ldg(bp + col + 1);
                float2 v0, v1;
                v0.x = acc[im][in][0] + b0; v0.y = acc[im][in][1] + b1;
                v1.x = acc[im][in][2] + b0; v1.y = acc[im][in][3] + b1;
                const int h = col >> 6, d0 = col & 63;
                const int bb0 = r0 >> 11, s0 = r0 & (S_ - 1);
                const int r1 = r0 + 8;
                const int bb1 = r1 >> 11, s1 = r1 & (S_ - 1);
                *(float2*)(dst0 + (((size_t)(bb0 * H_ + h) * S_ + s0) * DK_ + d0)) = v0;
                *(float2*)(dst0 + (((size_t)(bb1 * H_ + h) * S_ + s1) * DK_ + d0)) = v1;
            }
        }
    }
}

// ---------------------------------------------------------------------------
// Row softmax in-place + fp16 normalized copy. One block/row, float4, __expf.
// ---------------------------------------------------------------------------
__global__ __launch_bounds__(256) void softmax_kernel(
    float* __restrict__ attn, __half* __restrict__ patt)
{
    const size_t row = blockIdx.x;
    float4* p = (float4*)(attn + row * S_);
    uint2* p16 = (uint2*)(patt + row * S_);
    const int t = threadIdx.x;

    float4 v[2];
    float mx = -1e30f;
#pragma unroll
    for (int i = 0; i < 2; i++) {
        v[i] = p[t + 256 * i];
        mx = fmaxf(mx, fmaxf(fmaxf(v[i].x, v[i].y), fmaxf(v[i].z, v[i].w)));
    }
#pragma unroll
    for (int o = 16; o; o >>= 1) mx = fmaxf(mx, __shfl_xor_sync(0xffffffffu, mx, o));

    __shared__ float red[8];
    if ((t & 31) == 0) red[t >> 5] = mx;
    __syncthreads();
    mx = red[0];
#pragma unroll
    for (int i = 1; i < 8; i++) mx = fmaxf(mx, red[i]);
    __syncthreads();

    float sum = 0.f;
#pragma unroll
    for (int i = 0; i < 2; i++) {
        v[i].x = __expf(v[i].x - mx); v[i].y = __expf(v[i].y - mx);
        v[i].z = __expf(v[i].z - mx); v[i].w = __expf(v[i].w - mx);
        sum += (v[i].x + v[i].y) + (v[i].z + v[i].w);
    }
#pragma unroll
    for (int o = 16; o; o >>= 1) sum += __shfl_xor_sync(0xffffffffu, sum, o);
    if ((t & 31) == 0) red[t >> 5] = sum;
    __syncthreads();
    sum = 0.f;
#pragma unroll
    for (int i = 0; i < 8; i++) sum += red[i];

    const float inv = 1.0f / sum;
#pragma unroll
    for (int i = 0; i < 2; i++) {
        v[i].x *= inv; v[i].y *= inv; v[i].z *= inv; v[i].w *= inv;
        p[t + 256 * i] = v[i];
        __half2 a = __floats2half2_rn(v[i].x, v[i].y);
        __half2 b = __floats2half2_rn(v[i].z, v[i].w);
        uint2 u;
        u.x = *(uint32_t*)&a;
        u.y = *(uint32_t*)&b;
        p16[t + 256 * i] = u;
    }
}

// ---------------------------------------------------------------------------
// ctx: clean fp16 GEMM. A = patt [bh][s][2048] fp16, B = V^T hi/lo.
// Block 128x64, 8 warps (4x2, 32x32), BK=64, 3-stage cp.async.
// ---------------------------------------------------------------------------
#define CTX_STAGES 3
#define CTX_SMEM (CTX_STAGES * 32768)

__global__ __launch_bounds__(256, 2) void ctx_mma_kernel(
    const __half* __restrict__ patt, const __half* __restrict__ vth,
    const __half* __restrict__ vtl, __nv_bfloat16* __restrict__ xcat)
{
    extern __shared__ char smem[];
    const uint32_t sbase = smem_u32(smem);
    const int t = threadIdx.x, lane = t & 31, wid = t >> 5;
    const int wm = (wid >> 1) * 32, wn = (wid & 1) * 32;
    const int z = blockIdx.z, m0 = blockIdx.x * 128;

    const char* Ab = (const char*)(patt + ((size_t)z * S_ + m0) * S_);
    const char* Vh = (const char*)(vth + (size_t)z * DK_ * S_);
    const char* Vl = (const char*)(vtl + (size_t)z * DK_ * S_);

    auto load_stage = [&](int kt, int s) {
        const uint32_t sa = sbase + (uint32_t)s * 32768u;
#pragma unroll
        for (int i = 0; i < 4; i++) {            // A: 128 rows x 128B
            const int id = t + i * 256;
            const int row = id >> 3;
            const int cb = (id & 7) << 4;
            const uint32_t sw = SWZ128((uint32_t)(row * 128 + cb));
            cp_async16(sa + sw, Ab + (size_t)row * 4096 + (size_t)kt * 128 + cb);
        }
#pragma unroll
        for (int i = 0; i < 2; i++) {            // Vh + Vl: 64 rows x 128B each
            const int id = t + i * 256;
            const int row = id >> 3;
            const int cb = (id & 7) << 4;
            const uint32_t sw = SWZ128((uint32_t)(row * 128 + cb));
            const size_t g = (size_t)row * 4096 + (size_t)kt * 128 + cb;
            cp_async16(sa + 16384u + sw, Vh + g);
            cp_async16(sa + 24576u + sw, Vl + g);
        }
        CP_COMMIT();
    };

    float acc[2][4][4];
#pragma unroll
    for (int i = 0; i < 2; i++)
#pragma unroll
        for (int j = 0; j < 4; j++)
#pragma unroll
            for (int k = 0; k < 4; k++) acc[i][j][k] = 0.f;

    load_stage(0, 0);
    load_stage(1, 1);

    int st = 0;
    for (int kt = 0; kt < 32; kt++) {
        if (kt + 2 < 32) {
            int s2 = st + 2; if (s2 >= CTX_STAGES) s2 -= CTX_STAGES;
            load_stage(kt + 2, s2);
            CP_WAIT(2);
        } else {
            CP_WAIT(0);
        }
        __syncthreads();

        const uint32_t sa = sbase + (uint32_t)st * 32768u;

#pragma unroll
        for (int ks = 0; ks < 4; ks++) {
            uint32_t ah[2][4];
#pragma unroll
            for (int im = 0; im < 2; im++) {
                const int row = wm + im * 16 + (lane & 15);
                const int byt = ks * 32 + ((lane >> 4) << 4);
                ldsm4(ah[im], sa + SWZ128((uint32_t)(row * 128 + byt)));
            }
            uint32_t vhf[2][4], vlf[2][4];
#pragma unroll
            for (int j = 0; j < 2; j++) {
                const int nrow = wn + j * 16 + (lane & 7) + ((lane & 16) ? 8 : 0);
                const int byt = ks * 32 + ((lane & 8) ? 16 : 0);
                const uint32_t o = SWZ128((uint32_t)(nrow * 128 + byt));
                ldsm4(vhf[j], sa + 16384u + o);
                ldsm4(vlf[j], sa + 24576u + o);
            }
#pragma unroll
            for (int im = 0; im < 2; im++)
#pragma unroll
                for (int in = 0; in < 4; in++) {
                    const uint32_t* bh = &vhf[in >> 1][(in & 1) * 2];
                    const uint32_t* bl = &vlf[in >> 1][(in & 1) * 2];
                    mma_f16(acc[im][in], ah[im], bh[0], bh[1]);
                    mma_f16(acc[im][in], ah[im], bl[0], bl[1]);
                }
        }
        __syncthreads();
        st++; if (st >= CTX_STAGES) st = 0;
    }

    // epilogue: write xcat [hi|lo|hi]
    const int bb = z >> 4, h = z & 15;
#pragma unroll
    for (int im = 0; im < 2; im++) {
        const int r0 = m0 + wm + im * 16 + (lane >> 2);
#pragma unroll
        for (int in = 0; in < 4; in++) {
            const int col = wn + in * 8 + (lane & 3) * 2;
            const size_t xcol = (size_t)h * 64 + col;
#pragma unroll
            for (int half = 0; half < 2; half++) {
                const int r = r0 + half * 8;
                const float f0 = acc[im][in][half * 2 + 0];
                const float f1 = acc[im][in][half * 2 + 1];
                __nv_bfloat162 h2, l2;
                h2.x = __float2bfloat16(f0);
                h2.y = __float2bfloat16(f1);
                l2.x = __float2bfloat16(f0 - __bfloat162float(h2.x));
                l2.y = __float2bfloat16(f1 - __bfloat162float(h2.y));
                __nv_bfloat16* row = xcat + ((size_t)bb * S_ + r) * 3072;
                *(__nv_bfloat162*)(row + xcol)        = h2;
                *(__nv_bfloat162*)(row + 1024 + xcol) = l2;
                *(__nv_bfloat162*)(row + 2048 + xcol) = h2;
            }
        }
    }
}

// ---------------------------------------------------------------------------
extern "C" void kernel_launch(void* const* d_in, const int* in_sizes, int n_in,
                              void* d_out, int out_size)
{
    const float* q  = (const float*)d_in[0];
    const float* k  = (const float*)d_in[1];
    const float* v  = (const float*)d_in[2];
    const float* wq = (const float*)d_in[3];
    const float* bq = (const float*)d_in[4];
    const float* wk = (const float*)d_in[5];
    const float* bk = (const float*)d_in[6];
    const float* wv = (const float*)d_in[7];
    const float* bv = (const float*)d_in[8];
    const float* wo = (const float*)d_in[9];
    const float* bo = (const float*)d_in[10];

    float* out  = (float*)d_out;
    float* attn = out + OUT_ELEMS;

    float *qh, *kh, *vh;
    __nv_bfloat16 *xcat3, *wcat4, *qcat, *kcat;
    __half *vth, *vtl, *patt;
    cudaGetSymbolAddress((void**)&qh, g_qh);
    cudaGetSymbolAddress((void**)&kh, g_kh);
    cudaGetSymbolAddress((void**)&vh, g_vh);
    cudaGetSymbolAddress((void**)&xcat3, g_xcat3);
    cudaGetSymbolAddress((void**)&wcat4, g_wcat4);
    cudaGetSymbolAddress((void**)&qcat, g_qcat);
    cudaGetSymbolAddress((void**)&kcat, g_kcat);
    cudaGetSymbolAddress((void**)&vth, g_vth);
    cudaGetSymbolAddress((void**)&vtl, g_vtl);
    cudaGetSymbolAddress((void**)&patt, g_patt);

    cudaFuncSetAttribute(gemm_mma_kernel, cudaFuncAttributeMaxDynamicSharedMemorySize, GEMM_SMEM_SZ);
    cudaFuncSetAttribute(ctx_mma_kernel, cudaFuncAttributeMaxDynamicSharedMemorySize, CTX_SMEM);

    const long long secX = (long long)M_ * 3 * D_;
    const long long secW = (long long)D_ * 3 * D_;

    // 1. weight transposes (batched)
    transpose_split_cat4_kernel<<<dim3(32, 32, 4), 256>>>(wq, wk, wv, wo, wcat4);
    // 2. activation splits (batched z=3)
    split_cat3_kernel<<<dim3(M_ * 512 / 256, 3), 256>>>(q, k, v, xcat3);

    // 3. QKV projection (mode 1 -> qh/kh/vh fp32, head-split layout)
    gemm_mma_kernel<<<dim3(8, 32, 3), 256, GEMM_SMEM_SZ>>>(
        xcat3, 3 * D_, secX, wcat4, 3 * D_, secW,
        qh, D_, 0, bq, bk, bv, 1.0f, 3 * D_, 1, kh, vh);

    // 4. V^T fp16 hi/lo
    vtrans_kernel<<<dim3(S_ / 32, DK_ / 32, B_ * H_), 256>>>(vh, vth, vtl);
    // 5. Q/K head splits (batched z=2)
    splitqk_kernel<<<dim3((B_ * H_ * S_) * 32 / 256, 2), 256>>>(qh, kh, qcat, kcat);

    // 6. scores (mode 0, scale 1/8, no bias)
    gemm_mma_kernel<<<dim3(16, 16, 32), 256, GEMM_SMEM_SZ>>>(
        qcat, 3 * DK_, (long long)S_ * 3 * DK_,
        kcat, 3 * DK_, (long long)S_ * 3 * DK_,
        attn, S_, (long long)S_ * S_,
        nullptr, nullptr, nullptr, 0.125f, 3 * DK_, 0, nullptr, nullptr);

    // 7. softmax (in-place fp32 + fp16 copy)
    softmax_kernel<<<B_ * H_ * S_, 256>>>(attn, patt);

    // 8. ctx (pure fp16 GEMM, writes xcat3 sec 0)
    ctx_mma_kernel<<<dim3(16, 1, 32), 256, CTX_SMEM>>>(patt, vth, vtl, xcat3);

    // 9. output projection (mode 0 + bias)
    gemm_mma_kernel<<<dim3(8, 32, 1), 256, GEMM_SMEM_SZ>>>(
        xcat3, 3 * D_, 0, wcat4 + 3 * secW, 3 * D_, 0,
        out, D_, 0, bo, nullptr, nullptr, 1.0f, 3 * D_, 0, nullptr, nullptr);
}